// round 16
// baseline (speedup 1.0000x reference)
#include <cuda_runtime.h>
#include <cuda_bf16.h>
#include <math.h>
#include <stdint.h>

// Problem constants
#define B    32
#define NS   4096
#define D    256
#define H    4
#define LVL  6
#define NQ   512
#define NK   1024
#define DH   64
#define ATTN_SCALE 0.125f   // 1/sqrt(64), exact power of two

// ---------------------------------------------------------------------------
// Scratch (no allocations allowed -> device globals)
// ---------------------------------------------------------------------------
__device__ __nv_bfloat16 g_qnh[(size_t)B * NQ * D];
__device__ __nv_bfloat16 g_qnl[(size_t)B * NQ * D];
__device__ __nv_bfloat16 g_knh[(size_t)B * NK * D];
__device__ __nv_bfloat16 g_knl[(size_t)B * NK * D];
__device__ __nv_bfloat16 g_Qh [(size_t)B * NQ * D];
__device__ __nv_bfloat16 g_Ql [(size_t)B * NQ * D];
// interleaved K|V: [B*NK][512]
__device__ __nv_bfloat16 g_KVh[(size_t)B * NK * 512];
__device__ __nv_bfloat16 g_KVl[(size_t)B * NK * 512];
__device__ __nv_bfloat16 g_ctxh[(size_t)B * NQ * D];
__device__ __nv_bfloat16 g_ctxl[(size_t)B * NQ * D];
__device__ __nv_bfloat16 g_hh [(size_t)B * NQ * D];
__device__ __nv_bfloat16 g_hl [(size_t)B * NQ * D];
__device__ __nv_bfloat16 g_gh [(size_t)B * NQ * D];
__device__ __nv_bfloat16 g_gl [(size_t)B * NQ * D];

// transposed + bf16 hi/lo decomposed weights: [6][N=256][K=256]
__device__ __nv_bfloat16 g_Wt_hi[6 * 256 * 256];
__device__ __nv_bfloat16 g_Wt_lo[6 * 256 * 256];

// mask as bytes, all levels
__device__ unsigned char g_maskb[(size_t)LVL * NQ * NK];

// ---------------------------------------------------------------------------
// Helpers
// ---------------------------------------------------------------------------
__device__ __forceinline__ uint32_t smem_u32(const void* p) {
    uint32_t a;
    asm("{ .reg .u64 t; cvta.to.shared.u64 t, %1; cvt.u32.u64 %0, t; }" : "=r"(a) : "l"(p));
    return a;
}

__device__ __forceinline__ float gelu_tanh(float x) {
    float x3 = x * x * x;
    return 0.5f * x * (1.0f + tanhf(0.7978845608028654f * (x + 0.044715f * x3)));
}

__device__ __forceinline__ void mma16816(float* c, const uint32_t* a, uint32_t b0, uint32_t b1) {
    asm volatile(
        "mma.sync.aligned.m16n8k16.row.col.f32.bf16.bf16.f32 "
        "{%0,%1,%2,%3}, {%4,%5,%6,%7}, {%8,%9}, {%0,%1,%2,%3};"
        : "+f"(c[0]), "+f"(c[1]), "+f"(c[2]), "+f"(c[3])
        : "r"(a[0]), "r"(a[1]), "r"(a[2]), "r"(a[3]), "r"(b0), "r"(b1));
}

__device__ __forceinline__ void ldmatrix_x4(uint32_t* r, uint32_t addr) {
    asm volatile("ldmatrix.sync.aligned.m8n8.x4.shared.b16 {%0,%1,%2,%3}, [%4];"
                 : "=r"(r[0]), "=r"(r[1]), "=r"(r[2]), "=r"(r[3]) : "r"(addr));
}
__device__ __forceinline__ void ldmatrix_x4_t(uint32_t* r, uint32_t addr) {
    asm volatile("ldmatrix.sync.aligned.m8n8.x4.trans.shared.b16 {%0,%1,%2,%3}, [%4];"
                 : "=r"(r[0]), "=r"(r[1]), "=r"(r[2]), "=r"(r[3]) : "r"(addr));
}

__device__ __forceinline__ uint32_t packbf2(float x, float y) {
    __nv_bfloat162 h = __floats2bfloat162_rn(x, y);
    return *reinterpret_cast<uint32_t*>(&h);
}

__device__ __forceinline__ void split2(float x, float y, uint32_t& hp, uint32_t& lp) {
    __nv_bfloat16 h0 = __float2bfloat16(x);
    __nv_bfloat16 h1 = __float2bfloat16(y);
    hp = ((uint32_t)__bfloat16_as_ushort(h1) << 16) | __bfloat16_as_ushort(h0);
    lp = packbf2(x - __bfloat162float(h0), y - __bfloat162float(h1));
}

__device__ __forceinline__ float2 bf2_sum(uint32_t hp, uint32_t lp) {
    __nv_bfloat162 h2 = *reinterpret_cast<const __nv_bfloat162*>(&hp);
    __nv_bfloat162 l2 = *reinterpret_cast<const __nv_bfloat162*>(&lp);
    return make_float2(__bfloat162float(h2.x) + __bfloat162float(l2.x),
                       __bfloat162float(h2.y) + __bfloat162float(l2.y));
}

#define CP_ASYNC16(dst, src) \
    asm volatile("cp.async.cg.shared.global [%0], [%1], 16;" :: "r"(dst), "l"(src))
#define CP_COMMIT() asm volatile("cp.async.commit_group;" ::: "memory")
#define CP_WAIT1()  asm volatile("cp.async.wait_group 1;" ::: "memory")
#define CP_WAIT0()  asm volatile("cp.async.wait_group 0;" ::: "memory")

// PDL device hooks
#define PDL_SYNC()    cudaGridDependencySynchronize()
#define PDL_TRIGGER() cudaTriggerProgrammaticLaunchCompletion()

// warp-wide mean/rstd over 8 values per lane (row width 256)
__device__ __forceinline__ float2 warp_ln_stats(const float* v) {
    float s = 0.f, s2 = 0.f;
#pragma unroll
    for (int i = 0; i < 8; i++) { s += v[i]; s2 += v[i] * v[i]; }
#pragma unroll
    for (int o = 16; o > 0; o >>= 1) {
        s  += __shfl_xor_sync(0xffffffffu, s,  o);
        s2 += __shfl_xor_sync(0xffffffffu, s2, o);
    }
    float mean = s * (1.0f / D);
    float var  = s2 * (1.0f / D) - mean * mean;
    return make_float2(mean, rsqrtf(var + 1e-5f));
}

// ---------------------------------------------------------------------------
// init / mask / weight prep (plain launches, outside the PDL chain)
// ---------------------------------------------------------------------------
__global__ void init_kernel(float* __restrict__ outp) {
    size_t i = (size_t)blockIdx.x * blockDim.x + threadIdx.x;
    reinterpret_cast<float4*>(outp)[i] = make_float4(0.f, 0.f, 0.f, 0.f);
}

__global__ void maskb_kernel(const float* __restrict__ mask, unsigned char* __restrict__ mb) {
    size_t i = (size_t)blockIdx.x * 256 + threadIdx.x;
    float4 v = reinterpret_cast<const float4*>(mask)[i];
    uchar4 u;
    u.x = v.x > 0.5f; u.y = v.y > 0.5f; u.z = v.z > 0.5f; u.w = v.w > 0.5f;
    reinterpret_cast<uchar4*>(mb)[i] = u;
}

struct WPtrs { const float* w[6]; };

__global__ void prep_w_all_kernel(WPtrs ws,
                                  __nv_bfloat16* __restrict__ Th,
                                  __nv_bfloat16* __restrict__ Tl) {
    __shared__ float t[32][33];
    int wsel = blockIdx.z;
    const float* W = ws.w[wsel];
    __nv_bfloat16* Thw = Th + (size_t)wsel * 65536;
    __nv_bfloat16* Tlw = Tl + (size_t)wsel * 65536;
    int bx = blockIdx.x * 32;
    int by = blockIdx.y * 32;
#pragma unroll
    for (int i = threadIdx.y; i < 32; i += 8)
        t[i][threadIdx.x] = W[(size_t)(by + i) * 256 + bx + threadIdx.x];
    __syncthreads();
#pragma unroll
    for (int i = threadIdx.y; i < 32; i += 8) {
        float v = t[threadIdx.x][i];
        __nv_bfloat16 h = __float2bfloat16(v);
        float r = v - __bfloat162float(h);
        size_t o = (size_t)(bx + i) * 256 + by + threadIdx.x;
        Thw[o] = h;
        Tlw[o] = __float2bfloat16(r);
    }
}

// ---------------------------------------------------------------------------
// gather + LayerNorm(sys) -> bf16 hi/lo.  Warp per row; 8 rows per block.
// PDL: emb/upd0 loads pre-sync (static); outp read post-sync.
// ---------------------------------------------------------------------------
__global__ __launch_bounds__(256)
void gather_ln_kernel(const float* __restrict__ emb,
                      const float* __restrict__ upd0,
                      const float* __restrict__ outg,
                      const float* __restrict__ sscale,
                      const float* __restrict__ sbias,
                      const int* __restrict__ qidx,
                      const int* __restrict__ kidx,
                      __nv_bfloat16* __restrict__ qnh,
                      __nv_bfloat16* __restrict__ qnl,
                      __nv_bfloat16* __restrict__ knh,
                      __nv_bfloat16* __restrict__ knl) {
    int r = blockIdx.x * 8 + (threadIdx.x >> 5);
    int lane = threadIdx.x & 31;
    int col = lane * 8;
    int b, s;
    __nv_bfloat16 *dh, *dl;
    size_t off;
    if (r < B * NQ) {
        b = r / NQ;
        s = qidx[r % NQ];
        off = (size_t)r * D;
        dh = qnh; dl = qnl;
    } else {
        int r2 = r - B * NQ;
        b = r2 / NK;
        s = kidx[r2 % NK];
        off = (size_t)r2 * D;
        dh = knh; dl = knl;
    }
    size_t ub = ((size_t)b * NS + s) * D + col;
    // pre-sync: static inputs
    const float4* e4 = reinterpret_cast<const float4*>(emb + (size_t)s * D + col);
    const float4* u4 = reinterpret_cast<const float4*>(upd0 + ub);
    float4 a0 = e4[0], a1 = e4[1], b0 = u4[0], b1 = u4[1];
    float4 sc0 = reinterpret_cast<const float4*>(sscale + col)[0];
    float4 sc1 = reinterpret_cast<const float4*>(sscale + col)[1];
    float4 bi0 = reinterpret_cast<const float4*>(sbias + col)[0];
    float4 bi1 = reinterpret_cast<const float4*>(sbias + col)[1];

    PDL_SYNC();   // wait for upstream (previous level scatter into outg)

    const float4* o4 = reinterpret_cast<const float4*>(outg + ub);
    float4 c0 = o4[0], c1 = o4[1];
    float v[8];
    v[0] = a0.x + b0.x + c0.x; v[1] = a0.y + b0.y + c0.y;
    v[2] = a0.z + b0.z + c0.z; v[3] = a0.w + b0.w + c0.w;
    v[4] = a1.x + b1.x + c1.x; v[5] = a1.y + b1.y + c1.y;
    v[6] = a1.z + b1.z + c1.z; v[7] = a1.w + b1.w + c1.w;

    float2 st = warp_ln_stats(v);
    float sc[8] = {sc0.x, sc0.y, sc0.z, sc0.w, sc1.x, sc1.y, sc1.z, sc1.w};
    float bi[8] = {bi0.x, bi0.y, bi0.z, bi0.w, bi1.x, bi1.y, bi1.z, bi1.w};
    uint32_t hp[4], lp[4];
#pragma unroll
    for (int i = 0; i < 4; i++) {
        float y0 = (v[2*i]   - st.x) * st.y * sc[2*i]   + bi[2*i];
        float y1 = (v[2*i+1] - st.x) * st.y * sc[2*i+1] + bi[2*i+1];
        split2(y0, y1, hp[i], lp[i]);
    }
    PDL_TRIGGER();
    *reinterpret_cast<uint4*>(dh + off + col) = *reinterpret_cast<uint4*>(hp);
    *reinterpret_cast<uint4*>(dl + off + col) = *reinterpret_cast<uint4*>(lp);
}

// ---------------------------------------------------------------------------
// Shared 128x128 GEMM body (split-3, cp.async 2-stage), PDL-aware:
// chunk-0 B (weights, static) staged pre-sync; A staged post-sync.
// MODE: 0 plain, 2 +bias+gelu, 3 xATTN_SCALE.
// ---------------------------------------------------------------------------
#define GPAD 40
#define TILE_B (128 * GPAD * 2)
#define STAGE_B (4 * TILE_B)
#define GEMM_SMEM_BYTES (2 * STAGE_B)

__device__ __forceinline__ void gemm_issue_B(
    uint32_t stage, int tid,
    const __nv_bfloat16* Bh, const __nv_bfloat16* Bl,
    int nBase, int k0)
{
#pragma unroll
    for (int it = 0; it < 2; it++) {
        int seg = tid + it * 256;
        int row = seg >> 2, j = seg & 3;
        size_t go = (size_t)(nBase + row) * 256 + k0 + j * 8;
        uint32_t d = stage + 2 * TILE_B + (uint32_t)((row * GPAD + j * 8) * 2);
        CP_ASYNC16(d, Bh + go);
        CP_ASYNC16(d + TILE_B, Bl + go);
    }
}

__device__ __forceinline__ void gemm_issue_A(
    uint32_t stage, int tid,
    const __nv_bfloat16* Ah, const __nv_bfloat16* Al,
    int mBase, int k0)
{
#pragma unroll
    for (int it = 0; it < 2; it++) {
        int seg = tid + it * 256;
        int row = seg >> 2, j = seg & 3;
        size_t go = (size_t)(mBase + row) * 256 + k0 + j * 8;
        uint32_t d = stage + (uint32_t)((row * GPAD + j * 8) * 2);
        CP_ASYNC16(d, Ah + go);
        CP_ASYNC16(d + TILE_B, Al + go);
    }
}

template <int MODE>
__device__ __forceinline__ void gemm_body(
    char* smem,
    const __nv_bfloat16* __restrict__ Ah, const __nv_bfloat16* __restrict__ Al,
    const __nv_bfloat16* __restrict__ Bth, const __nv_bfloat16* __restrict__ Btl,
    const float* __restrict__ bias,
    __nv_bfloat16* __restrict__ Ch, __nv_bfloat16* __restrict__ Cl,
    int ldC, int mBase, int nBase)
{
    const uint32_t sb = smem_u32(smem);
    int tid  = threadIdx.x;
    int wid  = tid >> 5, lane = tid & 31;
    int warpM = wid & 3;
    int warpN = wid >> 2;

    float acc[2][8][4];
#pragma unroll
    for (int i = 0; i < 2; i++)
#pragma unroll
        for (int j = 0; j < 8; j++)
#pragma unroll
            for (int k = 0; k < 4; k++) acc[i][j][k] = 0.f;

    // PDL: weights are static -> prefetch before the dependency sync
    gemm_issue_B(sb, tid, Bth, Btl, nBase, 0);
    PDL_SYNC();
    gemm_issue_A(sb, tid, Ah, Al, mBase, 0);
    CP_COMMIT();

    for (int kc = 0; kc < 8; kc++) {
        if (kc < 7) {
            uint32_t ns = sb + ((kc + 1) & 1) * STAGE_B;
            gemm_issue_B(ns, tid, Bth, Btl, nBase, (kc + 1) * 32);
            gemm_issue_A(ns, tid, Ah, Al, mBase, (kc + 1) * 32);
            CP_COMMIT();
        }
        if (kc < 7) { CP_WAIT1(); } else { CP_WAIT0(); }
        __syncthreads();

        uint32_t st = sb + (kc & 1) * STAGE_B;
#pragma unroll
        for (int ks = 0; ks < 2; ks++) {
            int lrow = lane & 15;
            int lcol = ks * 16 + (lane >> 4) * 8;
            uint32_t ah[2][4], al[2][4];
#pragma unroll
            for (int mt = 0; mt < 2; mt++) {
                int row = warpM * 32 + mt * 16 + lrow;
                uint32_t ad = st + (uint32_t)((row * GPAD + lcol) * 2);
                ldmatrix_x4(ah[mt], ad);
                ldmatrix_x4(al[mt], ad + TILE_B);
            }
#pragma unroll
            for (int nt2 = 0; nt2 < 4; nt2++) {
                int row = warpN * 64 + nt2 * 16 + lrow;
                uint32_t bd = st + 2 * TILE_B + (uint32_t)((row * GPAD + lcol) * 2);
                uint32_t bh[4], bl[4];
                ldmatrix_x4(bh, bd);
                ldmatrix_x4(bl, bd + TILE_B);
#pragma unroll
                for (int mt = 0; mt < 2; mt++) {
                    mma16816(acc[mt][nt2 * 2 + 0], ah[mt], bh[0], bh[2]);
                    mma16816(acc[mt][nt2 * 2 + 0], ah[mt], bl[0], bl[2]);
                    mma16816(acc[mt][nt2 * 2 + 0], al[mt], bh[0], bh[2]);
                    mma16816(acc[mt][nt2 * 2 + 1], ah[mt], bh[1], bh[3]);
                    mma16816(acc[mt][nt2 * 2 + 1], ah[mt], bl[1], bl[3]);
                    mma16816(acc[mt][nt2 * 2 + 1], al[mt], bh[1], bh[3]);
                }
            }
        }
        __syncthreads();
    }

    PDL_TRIGGER();   // successor may start launching; epilogue still to run

    int g = lane >> 2, tig = lane & 3;
#pragma unroll
    for (int mt = 0; mt < 2; mt++) {
#pragma unroll
        for (int nt = 0; nt < 8; nt++) {
            int row0 = mBase + warpM * 32 + mt * 16 + g;
            int col  = nBase + warpN * 64 + nt * 8 + tig * 2;
            float v0 = acc[mt][nt][0], v1 = acc[mt][nt][1];
            float v2 = acc[mt][nt][2], v3 = acc[mt][nt][3];
            if (MODE == 2) {
                float bb0 = bias[col], bb1 = bias[col + 1];
                v0 = gelu_tanh(v0 + bb0); v1 = gelu_tanh(v1 + bb1);
                v2 = gelu_tanh(v2 + bb0); v3 = gelu_tanh(v3 + bb1);
            }
            if (MODE == 3) {
                v0 *= ATTN_SCALE; v1 *= ATTN_SCALE;
                v2 *= ATTN_SCALE; v3 *= ATTN_SCALE;
            }
            uint32_t hp01, lp01, hp23, lp23;
            split2(v0, v1, hp01, lp01);
            split2(v2, v3, hp23, lp23);
            *reinterpret_cast<uint32_t*>(Ch + (size_t)row0 * ldC + col) = hp01;
            *reinterpret_cast<uint32_t*>(Ch + (size_t)(row0 + 8) * ldC + col) = hp23;
            *reinterpret_cast<uint32_t*>(Cl + (size_t)row0 * ldC + col) = lp01;
            *reinterpret_cast<uint32_t*>(Cl + (size_t)(row0 + 8) * ldC + col) = lp23;
        }
    }
}

// ---------------------------------------------------------------------------
// Merged Q + K|V projection launch.
// ---------------------------------------------------------------------------
__global__ __launch_bounds__(256, 2)
void qkv_proj_kernel(const __nv_bfloat16* __restrict__ qnh, const __nv_bfloat16* __restrict__ qnl,
                     const __nv_bfloat16* __restrict__ knh, const __nv_bfloat16* __restrict__ knl,
                     const __nv_bfloat16* __restrict__ Wqh, const __nv_bfloat16* __restrict__ Wql,
                     const __nv_bfloat16* __restrict__ Wkvh, const __nv_bfloat16* __restrict__ Wkvl,
                     __nv_bfloat16* __restrict__ Qh, __nv_bfloat16* __restrict__ Ql,
                     __nv_bfloat16* __restrict__ KVh, __nv_bfloat16* __restrict__ KVl) {
    extern __shared__ char smem[];
    int bx = blockIdx.x;
    if (bx < (B * NK / 128) * 4) {
        gemm_body<0>(smem, knh, knl, Wkvh, Wkvl, nullptr,
                     KVh, KVl, 512, (bx >> 2) * 128, (bx & 3) * 128);
    } else {
        int b2 = bx - (B * NK / 128) * 4;
        gemm_body<3>(smem, qnh, qnl, Wqh, Wql, nullptr,
                     Qh, Ql, 256, (b2 >> 1) * 128, (b2 & 1) * 128);
    }
}

// W1 GEMM (bias + gelu)
__global__ __launch_bounds__(256, 2)
void gemm_w1_kernel(const __nv_bfloat16* __restrict__ Ah, const __nv_bfloat16* __restrict__ Al,
                    const __nv_bfloat16* __restrict__ Bth, const __nv_bfloat16* __restrict__ Btl,
                    const float* __restrict__ bias,
                    __nv_bfloat16* __restrict__ Ch, __nv_bfloat16* __restrict__ Cl) {
    extern __shared__ char smem[];
    gemm_body<2>(smem, Ah, Al, Bth, Btl, bias, Ch, Cl, 256,
                 blockIdx.x * 128, blockIdx.y * 128);
}

// ---------------------------------------------------------------------------
// GEMM 64(M) x 256(N) tile with fused row-LayerNorm epilogue. PDL-aware.
// ---------------------------------------------------------------------------
#define G2A (64 * GPAD * 2)
#define G2B (256 * GPAD * 2)
#define G2_STAGE (2 * G2A + 2 * G2B)
#define G2_SMEM (2 * G2_STAGE)

__device__ __forceinline__ void g2_issue_B(
    uint32_t stage, int tid,
    const __nv_bfloat16* Bh, const __nv_bfloat16* Bl, int k0)
{
#pragma unroll
    for (int it = 0; it < 4; it++) {
        int seg = tid + it * 256;
        int row = seg >> 2, j = seg & 3;
        uint32_t off = (uint32_t)((row * GPAD + j * 8) * 2);
        size_t go = (size_t)row * 256 + k0 + j * 8;
        CP_ASYNC16(stage + 2 * G2A + off, Bh + go);
        CP_ASYNC16(stage + 2 * G2A + G2B + off, Bl + go);
    }
}

__device__ __forceinline__ void g2_issue_A(
    uint32_t stage, int tid,
    const __nv_bfloat16* Ah, const __nv_bfloat16* Al,
    int mBase, int k0)
{
    int row = tid >> 2, j = tid & 3;
    uint32_t off = (uint32_t)((row * GPAD + j * 8) * 2);
    size_t go = (size_t)(mBase + row) * 256 + k0 + j * 8;
    CP_ASYNC16(stage + off, Ah + go);
    CP_ASYNC16(stage + G2A + off, Al + go);
}

__device__ __forceinline__ void cta_ln_stats(
    float (&acc)[2][8][4], char* smemraw,
    int warpM, int warpN, int g, int tig,
    float (&mean)[2][2], float (&rstd)[2][2])
{
    float* redS = reinterpret_cast<float*>(smemraw);
    float* redQ = redS + 256;
    __syncthreads();
    float ps[2][2], pq[2][2];
#pragma unroll
    for (int mt = 0; mt < 2; mt++)
#pragma unroll
        for (int hf = 0; hf < 2; hf++) {
            float s = 0.f, q = 0.f;
#pragma unroll
            for (int nt = 0; nt < 8; nt++) {
                float a = acc[mt][nt][hf * 2], b = acc[mt][nt][hf * 2 + 1];
                s += a + b; q += a * a + b * b;
            }
            ps[mt][hf] = s; pq[mt][hf] = q;
        }
#pragma unroll
    for (int o = 1; o <= 2; o <<= 1) {
#pragma unroll
        for (int mt = 0; mt < 2; mt++)
#pragma unroll
            for (int hf = 0; hf < 2; hf++) {
                ps[mt][hf] += __shfl_xor_sync(0xffffffffu, ps[mt][hf], o);
                pq[mt][hf] += __shfl_xor_sync(0xffffffffu, pq[mt][hf], o);
            }
    }
    if (tig == 0) {
#pragma unroll
        for (int mt = 0; mt < 2; mt++)
#pragma unroll
            for (int hf = 0; hf < 2; hf++) {
                int lr = warpM * 32 + mt * 16 + g + hf * 8;
                redS[lr * 4 + warpN] = ps[mt][hf];
                redQ[lr * 4 + warpN] = pq[mt][hf];
            }
    }
    __syncthreads();
#pragma unroll
    for (int mt = 0; mt < 2; mt++)
#pragma unroll
        for (int hf = 0; hf < 2; hf++) {
            int lr = warpM * 32 + mt * 16 + g + hf * 8;
            float S = redS[lr * 4] + redS[lr * 4 + 1] + redS[lr * 4 + 2] + redS[lr * 4 + 3];
            float Q = redQ[lr * 4] + redQ[lr * 4 + 1] + redQ[lr * 4 + 2] + redQ[lr * 4 + 3];
            float m = S * (1.0f / D);
            float v = Q * (1.0f / D) - m * m;
            mean[mt][hf] = m;
            rstd[mt][hf] = rsqrtf(v + 1e-5f);
        }
}

template <int RES>
__global__ __launch_bounds__(256, 2)
void gemm_ln_kernel(const __nv_bfloat16* __restrict__ Ah, const __nv_bfloat16* __restrict__ Al,
                    const __nv_bfloat16* __restrict__ Bth, const __nv_bfloat16* __restrict__ Btl,
                    const float* __restrict__ bias,
                    const float* __restrict__ ln1s, const float* __restrict__ ln1b,
                    const float* __restrict__ ln2s, const float* __restrict__ ln2b,
                    const __nv_bfloat16* __restrict__ hh, const __nv_bfloat16* __restrict__ hl,
                    const int* __restrict__ qidx,
                    __nv_bfloat16* __restrict__ Oh, __nv_bfloat16* __restrict__ Ol,
                    float* __restrict__ outp) {
    extern __shared__ char smem[];
    const uint32_t sb = smem_u32(smem);

    int tid  = threadIdx.x;
    int wid  = tid >> 5, lane = tid & 31;
    int warpM = wid & 1;
    int warpN = wid >> 1;
    int mBase = blockIdx.x * 64;
    int g = lane >> 2, tig = lane & 3;

    float acc[2][8][4];
#pragma unroll
    for (int i = 0; i < 2; i++)
#pragma unroll
        for (int j = 0; j < 8; j++)
#pragma unroll
            for (int k = 0; k < 4; k++) acc[i][j][k] = 0.f;

    // PDL: weights pre-sync, A post-sync
    g2_issue_B(sb, tid, Bth, Btl, 0);
    PDL_SYNC();
    g2_issue_A(sb, tid, Ah, Al, mBase, 0);
    CP_COMMIT();

    for (int kc = 0; kc < 8; kc++) {
        if (kc < 7) {
            uint32_t ns = sb + ((kc + 1) & 1) * G2_STAGE;
            g2_issue_B(ns, tid, Bth, Btl, (kc + 1) * 32);
            g2_issue_A(ns, tid, Ah, Al, mBase, (kc + 1) * 32);
            CP_COMMIT();
        }
        if (kc < 7) { CP_WAIT1(); } else { CP_WAIT0(); }
        __syncthreads();

        uint32_t st = sb + (kc & 1) * G2_STAGE;
#pragma unroll
        for (int ks = 0; ks < 2; ks++) {
            int lrow = lane & 15;
            int lcol = ks * 16 + (lane >> 4) * 8;
            uint32_t ah[2][4], al[2][4];
#pragma unroll
            for (int mt = 0; mt < 2; mt++) {
                int row = warpM * 32 + mt * 16 + lrow;
                uint32_t ad = st + (uint32_t)((row * GPAD + lcol) * 2);
                ldmatrix_x4(ah[mt], ad);
                ldmatrix_x4(al[mt], ad + G2A);
            }
#pragma unroll
            for (int nt2 = 0; nt2 < 4; nt2++) {
                int row = warpN * 64 + nt2 * 16 + lrow;
                uint32_t bd = st + 2 * G2A + (uint32_t)((row * GPAD + lcol) * 2);
                uint32_t bh[4], bl[4];
                ldmatrix_x4(bh, bd);
                ldmatrix_x4(bl, bd + G2B);
#pragma unroll
                for (int mt = 0; mt < 2; mt++) {
                    mma16816(acc[mt][nt2 * 2 + 0], ah[mt], bh[0], bh[2]);
                    mma16816(acc[mt][nt2 * 2 + 0], ah[mt], bl[0], bl[2]);
                    mma16816(acc[mt][nt2 * 2 + 0], al[mt], bh[0], bh[2]);
                    mma16816(acc[mt][nt2 * 2 + 1], ah[mt], bh[1], bh[3]);
                    mma16816(acc[mt][nt2 * 2 + 1], ah[mt], bl[1], bl[3]);
                    mma16816(acc[mt][nt2 * 2 + 1], al[mt], bh[1], bh[3]);
                }
            }
        }
        __syncthreads();
    }

    PDL_TRIGGER();

    float mean[2][2], rstd[2][2];

    if (RES == 1) {
#pragma unroll
        for (int mt = 0; mt < 2; mt++)
#pragma unroll
            for (int nt = 0; nt < 8; nt++) {
                int col = warpN * 64 + nt * 8 + tig * 2;
                float bb0 = __ldg(bias + col), bb1 = __ldg(bias + col + 1);
#pragma unroll
                for (int hf = 0; hf < 2; hf++) {
                    int gr = mBase + warpM * 32 + mt * 16 + g + hf * 8;
                    size_t o = (size_t)gr * D + col;
                    float2 hv = bf2_sum(*reinterpret_cast<const uint32_t*>(hh + o),
                                        *reinterpret_cast<const uint32_t*>(hl + o));
                    acc[mt][nt][hf * 2 + 0] += bb0 + hv.x;
                    acc[mt][nt][hf * 2 + 1] += bb1 + hv.y;
                }
            }
    }

    cta_ln_stats(acc, smem, warpM, warpN, g, tig, mean, rstd);
#pragma unroll
    for (int mt = 0; mt < 2; mt++)
#pragma unroll
        for (int nt = 0; nt < 8; nt++) {
            int col = warpN * 64 + nt * 8 + tig * 2;
            float s0 = __ldg(ln1s + col), s1 = __ldg(ln1s + col + 1);
            float c0 = __ldg(ln1b + col), c1 = __ldg(ln1b + col + 1);
#pragma unroll
            for (int hf = 0; hf < 2; hf++) {
                acc[mt][nt][hf * 2 + 0] =
                    (acc[mt][nt][hf * 2 + 0] - mean[mt][hf]) * rstd[mt][hf] * s0 + c0;
                acc[mt][nt][hf * 2 + 1] =
                    (acc[mt][nt][hf * 2 + 1] - mean[mt][hf]) * rstd[mt][hf] * s1 + c1;
            }
        }

    if (RES == 0) {
#pragma unroll
        for (int mt = 0; mt < 2; mt++)
#pragma unroll
            for (int nt = 0; nt < 8; nt++) {
                int col = warpN * 64 + nt * 8 + tig * 2;
#pragma unroll
                for (int hf = 0; hf < 2; hf++) {
                    int gr = mBase + warpM * 32 + mt * 16 + g + hf * 8;
                    uint32_t hp, lp;
                    split2(acc[mt][nt][hf * 2], acc[mt][nt][hf * 2 + 1], hp, lp);
                    *reinterpret_cast<uint32_t*>(Oh + (size_t)gr * D + col) = hp;
                    *reinterpret_cast<uint32_t*>(Ol + (size_t)gr * D + col) = lp;
                }
            }
    } else {
        cta_ln_stats(acc, smem, warpM, warpN, g, tig, mean, rstd);
        int sidx[2][2], bidx[2][2];
#pragma unroll
        for (int mt = 0; mt < 2; mt++)
#pragma unroll
            for (int hf = 0; hf < 2; hf++) {
                int gr = mBase + warpM * 32 + mt * 16 + g + hf * 8;
                bidx[mt][hf] = gr / NQ;
                sidx[mt][hf] = __ldg(qidx + (gr % NQ));
            }
#pragma unroll
        for (int mt = 0; mt < 2; mt++)
#pragma unroll
            for (int nt = 0; nt < 8; nt++) {
                int col = warpN * 64 + nt * 8 + tig * 2;
                float s0 = __ldg(ln2s + col), s1 = __ldg(ln2s + col + 1);
                float c0 = __ldg(ln2b + col), c1 = __ldg(ln2b + col + 1);
#pragma unroll
                for (int hf = 0; hf < 2; hf++) {
                    float z0 = (acc[mt][nt][hf * 2 + 0] - mean[mt][hf]) * rstd[mt][hf] * s0 + c0;
                    float z1 = (acc[mt][nt][hf * 2 + 1] - mean[mt][hf]) * rstd[mt][hf] * s1 + c1;
                    size_t o = ((size_t)bidx[mt][hf] * NS + sidx[mt][hf]) * D + col;
                    atomicAdd(&outp[o], z0);
                    atomicAdd(&outp[o + 1], z1);
                }
            }
    }
}

// ---------------------------------------------------------------------------
// Fused flash attention (static softmax, Q pre-scaled), Round-9 numerics.
// 256-query tile, 512 threads (16 warps): Q-tiles share staged K/V, halving
// K/V gmem traffic vs the 128-query tile. Per-warp work unchanged.
// PDL: mask chunk-0 staged pre-sync (static); Q/KV post-sync.
// ---------------------------------------------------------------------------
#define APAD 72
#define A_KH 0
#define A_KL 9216
#define A_VH 18432
#define A_VL 27648
#define A_MS 36864                      // 256 rows x 80 B mask = 20480
#define A_STAGE 57344
#define ATTN_SMEM_BYTES (2 * A_STAGE)   // 114688

__device__ __forceinline__ void attn_stage_mask(
    uint32_t st, int tid, const unsigned char* maskb, int q0, int kb)
{
#pragma unroll
    for (int it = 0; it < 2; it++) {
        int seg = tid + it * 512;        // 1024 segments: 256 rows x 4 (64B data, 80B stride)
        int r = seg >> 2, j = seg & 3;
        CP_ASYNC16(st + A_MS + (uint32_t)(r * 80 + j * 16),
                   maskb + (size_t)(q0 + r) * NK + kb + j * 16);
    }
}

__device__ __forceinline__ void attn_stage_kv(
    uint32_t st, int tid,
    const __nv_bfloat16* KVh, const __nv_bfloat16* KVl,
    int b, int h, int kb)
{
    // 512 segments: 64 rows x 8
    int r = tid >> 3, j = tid & 7;
    size_t rowb = ((size_t)(b * NK + kb + r)) * 512 + h * DH + j * 8;
    uint32_t off = (uint32_t)((r * APAD + j * 8) * 2);
    CP_ASYNC16(st + A_KH + off, KVh + rowb);
    CP_ASYNC16(st + A_KL + off, KVl + rowb);
    CP_ASYNC16(st + A_VH + off, KVh + rowb + 256);
    CP_ASYNC16(st + A_VL + off, KVl + rowb + 256);
}

__global__ __launch_bounds__(512, 1)
void attn_mma_kernel(const __nv_bfloat16* __restrict__ Qh, const __nv_bfloat16* __restrict__ Ql,
                     const __nv_bfloat16* __restrict__ KVh, const __nv_bfloat16* __restrict__ KVl,
                     const unsigned char* __restrict__ maskb,
                     __nv_bfloat16* __restrict__ ctxh, __nv_bfloat16* __restrict__ ctxl) {
    extern __shared__ char smem[];
    const uint32_t sb = smem_u32(smem);

    int tid = threadIdx.x, wid = tid >> 5, lane = tid & 31;
    int q0 = blockIdx.x * 256, h = blockIdx.y, b = blockIdx.z;
    int g = lane >> 2, tig = lane & 3;
    int lrow = lane & 15, lco = (lane >> 4) * 8;

    // PDL: mask is static -> stage chunk 0 mask before dependency sync
    attn_stage_mask(sb, tid, maskb, q0, 0);
    PDL_SYNC();
    attn_stage_kv(sb, tid, KVh, KVl, b, h, 0);
    CP_COMMIT();

    uint32_t qah[4][4], qal[4][4];
#pragma unroll
    for (int ks = 0; ks < 4; ks++) {
#pragma unroll
        for (int i = 0; i < 4; i++) {
            int row = q0 + wid * 16 + g + (i & 1) * 8;
            int col = h * DH + ks * 16 + tig * 2 + (i >> 1) * 8;
            size_t o = ((size_t)(b * NQ + row)) * D + col;
            qah[ks][i] = *reinterpret_cast<const uint32_t*>(Qh + o);
            qal[ks][i] = *reinterpret_cast<const uint32_t*>(Ql + o);
        }
    }

    float l0 = 0.f, l1 = 0.f;
    float oacc[8][4];
#pragma unroll
    for (int j = 0; j < 8; j++)
#pragma unroll
        for (int k = 0; k < 4; k++) oacc[j][k] = 0.f;

    for (int c = 0; c < 16; c++) {
        if (c < 15) {
            uint32_t ns = sb + ((c + 1) & 1) * A_STAGE;
            attn_stage_mask(ns, tid, maskb, q0, (c + 1) * 64);
            attn_stage_kv(ns, tid, KVh, KVl, b, h, (c + 1) * 64);
            CP_COMMIT();
        }
        if (c < 15) { CP_WAIT1(); } else { CP_WAIT0(); }
        __syncthreads();

        uint32_t st = sb + (c & 1) * A_STAGE;
        const unsigned char* msp = reinterpret_cast<const unsigned char*>(
            smem + (c & 1) * A_STAGE + A_MS);

        // S = Q K^T (split-3)
        float sacc[8][4];
#pragma unroll
        for (int j = 0; j < 8; j++)
#pragma unroll
            for (int k = 0; k < 4; k++) sacc[j][k] = 0.f;
#pragma unroll
        for (int ks = 0; ks < 4; ks++) {
#pragma unroll
            for (int nt = 0; nt < 4; nt++) {
                uint32_t bh[4], bl[4];
                uint32_t off = (uint32_t)(((nt * 16 + lrow) * APAD + ks * 16 + lco) * 2);
                ldmatrix_x4(bh, st + A_KH + off);
                ldmatrix_x4(bl, st + A_KL + off);
                mma16816(sacc[nt * 2 + 0], qah[ks], bh[0], bh[2]);
                mma16816(sacc[nt * 2 + 0], qah[ks], bl[0], bl[2]);
                mma16816(sacc[nt * 2 + 0], qal[ks], bh[0], bh[2]);
                mma16816(sacc[nt * 2 + 1], qah[ks], bh[1], bh[3]);
                mma16816(sacc[nt * 2 + 1], qah[ks], bl[1], bl[3]);
                mma16816(sacc[nt * 2 + 1], qal[ks], bh[1], bh[3]);
            }
        }

        // p = exp(s) masked->0; P split hi/lo; l in fp32 (unrounded)
        int qr0 = wid * 16 + g, qr1 = qr0 + 8;
        uint32_t pa[4][4], pl[4][4];
#pragma unroll
        for (int j = 0; j < 8; j++) {
            int col = j * 8 + 2 * tig;
            float p0 = msp[qr0 * 80 + col]     ? __expf(sacc[j][0]) : 0.f;
            float p1 = msp[qr0 * 80 + col + 1] ? __expf(sacc[j][1]) : 0.f;
            float p2 = msp[qr1 * 80 + col]     ? __expf(sacc[j][2]) : 0.f;
            float p3 = msp[qr1 * 80 + col + 1] ? __expf(sacc[j][3]) : 0.f;
            l0 += p0 + p1; l1 += p2 + p3;
            int kc = j >> 1, o2 = (j & 1) * 2;
            uint32_t hp, lp;
            split2(p0, p1, hp, lp);
            pa[kc][o2 + 0] = hp; pl[kc][o2 + 0] = lp;
            split2(p2, p3, hp, lp);
            pa[kc][o2 + 1] = hp; pl[kc][o2 + 1] = lp;
        }

        // O += P V  (split-3)
        int vro = ((lane >> 4) << 3) + (lane & 7);
        int vcb = ((lane >> 3) & 1) << 3;
#pragma unroll
        for (int kc = 0; kc < 4; kc++) {
            int vr = 16 * kc + vro;
#pragma unroll
            for (int vt = 0; vt < 4; vt++) {
                uint32_t vh[4], vl[4];
                uint32_t off = (uint32_t)((vr * APAD + vt * 16 + vcb) * 2);
                ldmatrix_x4_t(vh, st + A_VH + off);
                ldmatrix_x4_t(vl, st + A_VL + off);
                mma16816(oacc[vt * 2 + 0], pa[kc], vh[0], vh[2]);
                mma16816(oacc[vt * 2 + 0], pa[kc], vl[0], vl[2]);
                mma16816(oacc[vt * 2 + 0], pl[kc], vh[0], vh[2]);
                mma16816(oacc[vt * 2 + 1], pa[kc], vh[1], vh[3]);
                mma16816(oacc[vt * 2 + 1], pa[kc], vl[1], vl[3]);
                mma16816(oacc[vt * 2 + 1], pl[kc], vh[1], vh[3]);
            }
        }
        __syncthreads();
    }

    PDL_TRIGGER();

    l0 += __shfl_xor_sync(0xffffffffu, l0, 1);
    l0 += __shfl_xor_sync(0xffffffffu, l0, 2);
    l1 += __shfl_xor_sync(0xffffffffu, l1, 1);
    l1 += __shfl_xor_sync(0xffffffffu, l1, 2);

    float inv0 = 1.0f / l0, inv1 = 1.0f / l1;
#pragma unroll
    for (int j = 0; j < 8; j++) {
        int col = h * DH + j * 8 + 2 * tig;
        size_t r0 = ((size_t)(b * NQ + q0 + wid * 16 + g)) * D + col;
        uint32_t hp, lp;
        split2(oacc[j][0] * inv0, oacc[j][1] * inv0, hp, lp);
        *reinterpret_cast<uint32_t*>(ctxh + r0) = hp;
        *reinterpret_cast<uint32_t*>(ctxl + r0) = lp;
        split2(oacc[j][2] * inv1, oacc[j][3] * inv1, hp, lp);
        *reinterpret_cast<uint32_t*>(ctxh + r0 + 8 * D) = hp;
        *reinterpret_cast<uint32_t*>(ctxl + r0 + 8 * D) = lp;
    }
}

// ---------------------------------------------------------------------------
// launch
// ---------------------------------------------------------------------------
extern "C" void kernel_launch(void* const* d_in, const int* in_sizes, int n_in,
                              void* d_out, int out_size) {
    const float* update_tensor = (const float*)d_in[0];
    const float* emb   = (const float*)d_in[1];
    const float* mask  = (const float*)d_in[2];
    const float* Wq    = (const float*)d_in[3];
    const float* Wk    = (const float*)d_in[4];
    const float* Wv    = (const float*)d_in[5];
    const float* Wo    = (const float*)d_in[6];
    const float* W1    = (const float*)d_in[7];
    const float* b1    = (const float*)d_in[8];
    const float* W2    = (const float*)d_in[9];
    const float* b2    = (const float*)d_in[10];
    const float* sys_s = (const float*)d_in[11];
    const float* sys_b = (const float*)d_in[12];
    const float* eff_s = (const float*)d_in[13];
    const float* eff_b = (const float*)d_in[14];
    const float* in_s  = (const float*)d_in[15];
    const float* in_b  = (const float*)d_in[16];
    const float* out_s = (const float*)d_in[17];
    const float* out_b = (const float*)d_in[18];
    const int*   qidx  = (const int*)d_in[19];
    const int*   kidx  = (const int*)d_in[20];
    float* outp = (float*)d_out;

    __nv_bfloat16 *p_wh, *p_wl, *p_qnh, *p_qnl, *p_knh, *p_knl;
    __nv_bfloat16 *p_Qh, *p_Ql, *p_KVh, *p_KVl;
    __nv_bfloat16 *p_ctxh, *p_ctxl, *p_hh, *p_hl, *p_gh, *p_gl;
    unsigned char* p_mb;
    cudaGetSymbolAddress((void**)&p_wh,   g_Wt_hi);
    cudaGetSymbolAddress((void**)&p_wl,   g_Wt_lo);
    cudaGetSymbolAddress((void**)&p_qnh,  g_qnh);
    cudaGetSymbolAddress((void**)&p_qnl,  g_qnl);
    cudaGetSymbolAddress((void**)&p_knh,  g_knh);
    cudaGetSymbolAddress((void**)&p_knl,  g_knl);
    cudaGetSymbolAddress((void**)&p_Qh,   g_Qh);
    cudaGetSymbolAddress((void**)&p_Ql,   g_Ql);
    cudaGetSymbolAddress((void**)&p_KVh,  g_KVh);
    cudaGetSymbolAddress((void**)&p_KVl,  g_KVl);
    cudaGetSymbolAddress((void**)&p_ctxh, g_ctxh);
    cudaGetSymbolAddress((void**)&p_ctxl, g_ctxl);
    cudaGetSymbolAddress((void**)&p_hh,   g_hh);
    cudaGetSymbolAddress((void**)&p_hl,   g_hl);
    cudaGetSymbolAddress((void**)&p_gh,   g_gh);
    cudaGetSymbolAddress((void**)&p_gl,   g_gl);
    cudaGetSymbolAddress((void**)&p_mb,   g_maskb);

    cudaFuncSetAttribute(qkv_proj_kernel, cudaFuncAttributeMaxDynamicSharedMemorySize, GEMM_SMEM_BYTES);
    cudaFuncSetAttribute(gemm_w1_kernel,  cudaFuncAttributeMaxDynamicSharedMemorySize, GEMM_SMEM_BYTES);
    cudaFuncSetAttribute(gemm_ln_kernel<0>, cudaFuncAttributeMaxDynamicSharedMemorySize, G2_SMEM);
    cudaFuncSetAttribute(gemm_ln_kernel<1>, cudaFuncAttributeMaxDynamicSharedMemorySize, G2_SMEM);
    cudaFuncSetAttribute(attn_mma_kernel, cudaFuncAttributeMaxDynamicSharedMemorySize, ATTN_SMEM_BYTES);

    init_kernel<<<(B * NS * D / 4) / 256, 256>>>(outp);
    maskb_kernel<<<(LVL * NQ * NK / 4) / 256, 256>>>(mask, p_mb);
    {
        WPtrs ws;
        ws.w[0] = Wq; ws.w[1] = Wk; ws.w[2] = Wv;
        ws.w[3] = Wo; ws.w[4] = W1; ws.w[5] = W2;
        prep_w_all_kernel<<<dim3(8, 8, 6), dim3(32, 8)>>>(ws, p_wh, p_wl);
    }

    const int QKV_GRID = (B * NK / 128) * 4 + (B * NQ / 128) * 2;   // 1280

    cudaLaunchAttribute pdlAttr[1];
    pdlAttr[0].id = cudaLaunchAttributeProgrammaticStreamSerialization;
    pdlAttr[0].val.programmaticStreamSerializationAllowed = 1;

    cudaLaunchConfig_t cGather = {};
    cGather.gridDim = dim3(B * (NQ + NK) / 8, 1, 1);
    cGather.blockDim = dim3(256, 1, 1);
    cGather.attrs = pdlAttr; cGather.numAttrs = 1;

    cudaLaunchConfig_t cQkv = {};
    cQkv.gridDim = dim3(QKV_GRID, 1, 1);
    cQkv.blockDim = dim3(256, 1, 1);
    cQkv.dynamicSmemBytes = GEMM_SMEM_BYTES;
    cQkv.attrs = pdlAttr; cQkv.numAttrs = 1;

    cudaLaunchConfig_t cAttn = {};
    cAttn.gridDim = dim3(NQ / 256, H, B);
    cAttn.blockDim = dim3(512, 1, 1);
    cAttn.dynamicSmemBytes = ATTN_SMEM_BYTES;
    cAttn.attrs = pdlAttr; cAttn.numAttrs = 1;

    cudaLaunchConfig_t cLn = {};
    cLn.gridDim = dim3(B * NQ / 64, 1, 1);
    cLn.blockDim = dim3(256, 1, 1);
    cLn.dynamicSmemBytes = G2_SMEM;
    cLn.attrs = pdlAttr; cLn.numAttrs = 1;

    cudaLaunchConfig_t cW1 = {};
    cW1.gridDim = dim3(B * NQ / 128, 2, 1);
    cW1.blockDim = dim3(256, 1, 1);
    cW1.dynamicSmemBytes = GEMM_SMEM_BYTES;
    cW1.attrs = pdlAttr; cW1.numAttrs = 1;

    for (int l = 0; l < LVL; l++) {
        const int* qi = qidx + l * NQ;
        const int* ki = kidx + l * NK;
        const unsigned char* mb = p_mb + (size_t)l * NQ * NK;

        cudaLaunchKernelEx(&cGather, gather_ln_kernel,
                           emb, update_tensor, (const float*)outp,
                           sys_s, sys_b, qi, ki,
                           p_qnh, p_qnl, p_knh, p_knl);

        cudaLaunchKernelEx(&cQkv, qkv_proj_kernel,
                           (const __nv_bfloat16*)p_qnh, (const __nv_bfloat16*)p_qnl,
                           (const __nv_bfloat16*)p_knh, (const __nv_bfloat16*)p_knl,
                           (const __nv_bfloat16*)(p_wh + 0 * 65536), (const __nv_bfloat16*)(p_wl + 0 * 65536),
                           (const __nv_bfloat16*)(p_wh + 1 * 65536), (const __nv_bfloat16*)(p_wl + 1 * 65536),
                           p_Qh, p_Ql, p_KVh, p_KVl);

        cudaLaunchKernelEx(&cAttn, attn_mma_kernel,
                           (const __nv_bfloat16*)p_Qh, (const __nv_bfloat16*)p_Ql,
                           (const __nv_bfloat16*)p_KVh, (const __nv_bfloat16*)p_KVl,
                           (const unsigned char*)mb, p_ctxh, p_ctxl);

        cudaLaunchKernelEx(&cLn, gemm_ln_kernel<0>,
                           (const __nv_bfloat16*)p_ctxh, (const __nv_bfloat16*)p_ctxl,
                           (const __nv_bfloat16*)(p_wh + 3 * 65536), (const __nv_bfloat16*)(p_wl + 3 * 65536),
                           (const float*)nullptr, in_s, in_b,
                           (const float*)nullptr, (const float*)nullptr,
                           (const __nv_bfloat16*)nullptr, (const __nv_bfloat16*)nullptr,
                           (const int*)nullptr, p_hh, p_hl, (float*)nullptr);

        cudaLaunchKernelEx(&cW1, gemm_w1_kernel,
                           (const __nv_bfloat16*)p_hh, (const __nv_bfloat16*)p_hl,
                           (const __nv_bfloat16*)(p_wh + 4 * 65536), (const __nv_bfloat16*)(p_wl + 4 * 65536),
                           b1, p_gh, p_gl);

        cudaLaunchKernelEx(&cLn, gemm_ln_kernel<1>,
                           (const __nv_bfloat16*)p_gh, (const __nv_bfloat16*)p_gl,
                           (const __nv_bfloat16*)(p_wh + 5 * 65536), (const __nv_bfloat16*)(p_wl + 5 * 65536),
                           b2, out_s, out_b, eff_s, eff_b,
                           (const __nv_bfloat16*)p_hh, (const __nv_bfloat16*)p_hl,
                           qi, (__nv_bfloat16*)nullptr, (__nv_bfloat16*)nullptr, outp);
    }
}

// round 17
// speedup vs baseline: 1.0259x; 1.0259x over previous
#include <cuda_runtime.h>
#include <cuda_bf16.h>
#include <math.h>
#include <stdint.h>

// Problem constants
#define B    32
#define NS   4096
#define D    256
#define H    4
#define LVL  6
#define NQ   512
#define NK   1024
#define DH   64
#define ATTN_SCALE 0.125f   // 1/sqrt(64), exact power of two

// ---------------------------------------------------------------------------
// Scratch (no allocations allowed -> device globals)
// ---------------------------------------------------------------------------
__device__ __nv_bfloat16 g_qnh[(size_t)B * NQ * D];
__device__ __nv_bfloat16 g_qnl[(size_t)B * NQ * D];
__device__ __nv_bfloat16 g_knh[(size_t)B * NK * D];
__device__ __nv_bfloat16 g_knl[(size_t)B * NK * D];
__device__ __nv_bfloat16 g_Qh [(size_t)B * NQ * D];
__device__ __nv_bfloat16 g_Ql [(size_t)B * NQ * D];
// interleaved K|V: [B*NK][512]
__device__ __nv_bfloat16 g_KVh[(size_t)B * NK * 512];
__device__ __nv_bfloat16 g_KVl[(size_t)B * NK * 512];
__device__ __nv_bfloat16 g_ctxh[(size_t)B * NQ * D];
__device__ __nv_bfloat16 g_ctxl[(size_t)B * NQ * D];
__device__ __nv_bfloat16 g_hh [(size_t)B * NQ * D];
__device__ __nv_bfloat16 g_hl [(size_t)B * NQ * D];
__device__ __nv_bfloat16 g_gh [(size_t)B * NQ * D];
__device__ __nv_bfloat16 g_gl [(size_t)B * NQ * D];

// transposed + bf16 hi/lo decomposed weights: [6][N=256][K=256]
__device__ __nv_bfloat16 g_Wt_hi[6 * 256 * 256];
__device__ __nv_bfloat16 g_Wt_lo[6 * 256 * 256];

// mask as bytes, all levels
__device__ unsigned char g_maskb[(size_t)LVL * NQ * NK];

// ---------------------------------------------------------------------------
// Helpers
// ---------------------------------------------------------------------------
__device__ __forceinline__ uint32_t smem_u32(const void* p) {
    uint32_t a;
    asm("{ .reg .u64 t; cvta.to.shared.u64 t, %1; cvt.u32.u64 %0, t; }" : "=r"(a) : "l"(p));
    return a;
}

__device__ __forceinline__ float gelu_tanh(float x) {
    float x3 = x * x * x;
    return 0.5f * x * (1.0f + tanhf(0.7978845608028654f * (x + 0.044715f * x3)));
}

__device__ __forceinline__ void mma16816(float* c, const uint32_t* a, uint32_t b0, uint32_t b1) {
    asm volatile(
        "mma.sync.aligned.m16n8k16.row.col.f32.bf16.bf16.f32 "
        "{%0,%1,%2,%3}, {%4,%5,%6,%7}, {%8,%9}, {%0,%1,%2,%3};"
        : "+f"(c[0]), "+f"(c[1]), "+f"(c[2]), "+f"(c[3])
        : "r"(a[0]), "r"(a[1]), "r"(a[2]), "r"(a[3]), "r"(b0), "r"(b1));
}

__device__ __forceinline__ void ldmatrix_x4(uint32_t* r, uint32_t addr) {
    asm volatile("ldmatrix.sync.aligned.m8n8.x4.shared.b16 {%0,%1,%2,%3}, [%4];"
                 : "=r"(r[0]), "=r"(r[1]), "=r"(r[2]), "=r"(r[3]) : "r"(addr));
}
__device__ __forceinline__ void ldmatrix_x4_t(uint32_t* r, uint32_t addr) {
    asm volatile("ldmatrix.sync.aligned.m8n8.x4.trans.shared.b16 {%0,%1,%2,%3}, [%4];"
                 : "=r"(r[0]), "=r"(r[1]), "=r"(r[2]), "=r"(r[3]) : "r"(addr));
}

__device__ __forceinline__ uint32_t packbf2(float x, float y) {
    __nv_bfloat162 h = __floats2bfloat162_rn(x, y);
    return *reinterpret_cast<uint32_t*>(&h);
}

__device__ __forceinline__ void split2(float x, float y, uint32_t& hp, uint32_t& lp) {
    __nv_bfloat16 h0 = __float2bfloat16(x);
    __nv_bfloat16 h1 = __float2bfloat16(y);
    hp = ((uint32_t)__bfloat16_as_ushort(h1) << 16) | __bfloat16_as_ushort(h0);
    lp = packbf2(x - __bfloat162float(h0), y - __bfloat162float(h1));
}

__device__ __forceinline__ float2 bf2_sum(uint32_t hp, uint32_t lp) {
    __nv_bfloat162 h2 = *reinterpret_cast<const __nv_bfloat162*>(&hp);
    __nv_bfloat162 l2 = *reinterpret_cast<const __nv_bfloat162*>(&lp);
    return make_float2(__bfloat162float(h2.x) + __bfloat162float(l2.x),
                       __bfloat162float(h2.y) + __bfloat162float(l2.y));
}

#define CP_ASYNC16(dst, src) \
    asm volatile("cp.async.cg.shared.global [%0], [%1], 16;" :: "r"(dst), "l"(src))
#define CP_COMMIT() asm volatile("cp.async.commit_group;" ::: "memory")
#define CP_WAIT1()  asm volatile("cp.async.wait_group 1;" ::: "memory")
#define CP_WAIT0()  asm volatile("cp.async.wait_group 0;" ::: "memory")

// PDL device hooks
#define PDL_SYNC()    cudaGridDependencySynchronize()
#define PDL_TRIGGER() cudaTriggerProgrammaticLaunchCompletion()

// warp-wide mean/rstd over 8 values per lane (row width 256)
__device__ __forceinline__ float2 warp_ln_stats(const float* v) {
    float s = 0.f, s2 = 0.f;
#pragma unroll
    for (int i = 0; i < 8; i++) { s += v[i]; s2 += v[i] * v[i]; }
#pragma unroll
    for (int o = 16; o > 0; o >>= 1) {
        s  += __shfl_xor_sync(0xffffffffu, s,  o);
        s2 += __shfl_xor_sync(0xffffffffu, s2, o);
    }
    float mean = s * (1.0f / D);
    float var  = s2 * (1.0f / D) - mean * mean;
    return make_float2(mean, rsqrtf(var + 1e-5f));
}

// ---------------------------------------------------------------------------
// init / mask / weight prep (plain launches, outside the PDL chain)
// ---------------------------------------------------------------------------
__global__ void init_kernel(float* __restrict__ outp) {
    size_t i = (size_t)blockIdx.x * blockDim.x + threadIdx.x;
    reinterpret_cast<float4*>(outp)[i] = make_float4(0.f, 0.f, 0.f, 0.f);
}

__global__ void maskb_kernel(const float* __restrict__ mask, unsigned char* __restrict__ mb) {
    size_t i = (size_t)blockIdx.x * 256 + threadIdx.x;
    float4 v = reinterpret_cast<const float4*>(mask)[i];
    uchar4 u;
    u.x = v.x > 0.5f; u.y = v.y > 0.5f; u.z = v.z > 0.5f; u.w = v.w > 0.5f;
    reinterpret_cast<uchar4*>(mb)[i] = u;
}

struct WPtrs { const float* w[6]; };

__global__ void prep_w_all_kernel(WPtrs ws,
                                  __nv_bfloat16* __restrict__ Th,
                                  __nv_bfloat16* __restrict__ Tl) {
    __shared__ float t[32][33];
    int wsel = blockIdx.z;
    const float* W = ws.w[wsel];
    __nv_bfloat16* Thw = Th + (size_t)wsel * 65536;
    __nv_bfloat16* Tlw = Tl + (size_t)wsel * 65536;
    int bx = blockIdx.x * 32;
    int by = blockIdx.y * 32;
#pragma unroll
    for (int i = threadIdx.y; i < 32; i += 8)
        t[i][threadIdx.x] = W[(size_t)(by + i) * 256 + bx + threadIdx.x];
    __syncthreads();
#pragma unroll
    for (int i = threadIdx.y; i < 32; i += 8) {
        float v = t[threadIdx.x][i];
        __nv_bfloat16 h = __float2bfloat16(v);
        float r = v - __bfloat162float(h);
        size_t o = (size_t)(bx + i) * 256 + by + threadIdx.x;
        Thw[o] = h;
        Tlw[o] = __float2bfloat16(r);
    }
}

// ---------------------------------------------------------------------------
// gather + LayerNorm(sys) -> bf16 hi/lo.  Warp per row; 8 rows per block.
// PDL: emb/upd0 loads pre-sync (static); outp read post-sync.
// ---------------------------------------------------------------------------
__global__ __launch_bounds__(256)
void gather_ln_kernel(const float* __restrict__ emb,
                      const float* __restrict__ upd0,
                      const float* __restrict__ outg,
                      const float* __restrict__ sscale,
                      const float* __restrict__ sbias,
                      const int* __restrict__ qidx,
                      const int* __restrict__ kidx,
                      __nv_bfloat16* __restrict__ qnh,
                      __nv_bfloat16* __restrict__ qnl,
                      __nv_bfloat16* __restrict__ knh,
                      __nv_bfloat16* __restrict__ knl) {
    int r = blockIdx.x * 8 + (threadIdx.x >> 5);
    int lane = threadIdx.x & 31;
    int col = lane * 8;
    int b, s;
    __nv_bfloat16 *dh, *dl;
    size_t off;
    if (r < B * NQ) {
        b = r / NQ;
        s = qidx[r % NQ];
        off = (size_t)r * D;
        dh = qnh; dl = qnl;
    } else {
        int r2 = r - B * NQ;
        b = r2 / NK;
        s = kidx[r2 % NK];
        off = (size_t)r2 * D;
        dh = knh; dl = knl;
    }
    size_t ub = ((size_t)b * NS + s) * D + col;
    // pre-sync: static inputs
    const float4* e4 = reinterpret_cast<const float4*>(emb + (size_t)s * D + col);
    const float4* u4 = reinterpret_cast<const float4*>(upd0 + ub);
    float4 a0 = e4[0], a1 = e4[1], b0 = u4[0], b1 = u4[1];
    float4 sc0 = reinterpret_cast<const float4*>(sscale + col)[0];
    float4 sc1 = reinterpret_cast<const float4*>(sscale + col)[1];
    float4 bi0 = reinterpret_cast<const float4*>(sbias + col)[0];
    float4 bi1 = reinterpret_cast<const float4*>(sbias + col)[1];

    PDL_SYNC();   // wait for upstream (previous level scatter into outg)

    const float4* o4 = reinterpret_cast<const float4*>(outg + ub);
    float4 c0 = o4[0], c1 = o4[1];
    float v[8];
    v[0] = a0.x + b0.x + c0.x; v[1] = a0.y + b0.y + c0.y;
    v[2] = a0.z + b0.z + c0.z; v[3] = a0.w + b0.w + c0.w;
    v[4] = a1.x + b1.x + c1.x; v[5] = a1.y + b1.y + c1.y;
    v[6] = a1.z + b1.z + c1.z; v[7] = a1.w + b1.w + c1.w;

    float2 st = warp_ln_stats(v);
    float sc[8] = {sc0.x, sc0.y, sc0.z, sc0.w, sc1.x, sc1.y, sc1.z, sc1.w};
    float bi[8] = {bi0.x, bi0.y, bi0.z, bi0.w, bi1.x, bi1.y, bi1.z, bi1.w};
    uint32_t hp[4], lp[4];
#pragma unroll
    for (int i = 0; i < 4; i++) {
        float y0 = (v[2*i]   - st.x) * st.y * sc[2*i]   + bi[2*i];
        float y1 = (v[2*i+1] - st.x) * st.y * sc[2*i+1] + bi[2*i+1];
        split2(y0, y1, hp[i], lp[i]);
    }
    PDL_TRIGGER();
    *reinterpret_cast<uint4*>(dh + off + col) = *reinterpret_cast<uint4*>(hp);
    *reinterpret_cast<uint4*>(dl + off + col) = *reinterpret_cast<uint4*>(lp);
}

// ---------------------------------------------------------------------------
// Shared 128x128 GEMM body (split-3, cp.async 2-stage), PDL-aware:
// chunk-0 B (weights, static) staged pre-sync; A staged post-sync.
// MODE: 0 plain, 2 +bias+gelu, 3 xATTN_SCALE.
// ---------------------------------------------------------------------------
#define GPAD 40
#define TILE_B (128 * GPAD * 2)
#define STAGE_B (4 * TILE_B)
#define GEMM_SMEM_BYTES (2 * STAGE_B)

__device__ __forceinline__ void gemm_issue_B(
    uint32_t stage, int tid,
    const __nv_bfloat16* Bh, const __nv_bfloat16* Bl,
    int nBase, int k0)
{
#pragma unroll
    for (int it = 0; it < 2; it++) {
        int seg = tid + it * 256;
        int row = seg >> 2, j = seg & 3;
        size_t go = (size_t)(nBase + row) * 256 + k0 + j * 8;
        uint32_t d = stage + 2 * TILE_B + (uint32_t)((row * GPAD + j * 8) * 2);
        CP_ASYNC16(d, Bh + go);
        CP_ASYNC16(d + TILE_B, Bl + go);
    }
}

__device__ __forceinline__ void gemm_issue_A(
    uint32_t stage, int tid,
    const __nv_bfloat16* Ah, const __nv_bfloat16* Al,
    int mBase, int k0)
{
#pragma unroll
    for (int it = 0; it < 2; it++) {
        int seg = tid + it * 256;
        int row = seg >> 2, j = seg & 3;
        size_t go = (size_t)(mBase + row) * 256 + k0 + j * 8;
        uint32_t d = stage + (uint32_t)((row * GPAD + j * 8) * 2);
        CP_ASYNC16(d, Ah + go);
        CP_ASYNC16(d + TILE_B, Al + go);
    }
}

template <int MODE>
__device__ __forceinline__ void gemm_body(
    char* smem,
    const __nv_bfloat16* __restrict__ Ah, const __nv_bfloat16* __restrict__ Al,
    const __nv_bfloat16* __restrict__ Bth, const __nv_bfloat16* __restrict__ Btl,
    const float* __restrict__ bias,
    __nv_bfloat16* __restrict__ Ch, __nv_bfloat16* __restrict__ Cl,
    int ldC, int mBase, int nBase)
{
    const uint32_t sb = smem_u32(smem);
    int tid  = threadIdx.x;
    int wid  = tid >> 5, lane = tid & 31;
    int warpM = wid & 3;
    int warpN = wid >> 2;

    float acc[2][8][4];
#pragma unroll
    for (int i = 0; i < 2; i++)
#pragma unroll
        for (int j = 0; j < 8; j++)
#pragma unroll
            for (int k = 0; k < 4; k++) acc[i][j][k] = 0.f;

    // PDL: weights are static -> prefetch before the dependency sync
    gemm_issue_B(sb, tid, Bth, Btl, nBase, 0);
    PDL_SYNC();
    gemm_issue_A(sb, tid, Ah, Al, mBase, 0);
    CP_COMMIT();

    for (int kc = 0; kc < 8; kc++) {
        if (kc < 7) {
            uint32_t ns = sb + ((kc + 1) & 1) * STAGE_B;
            gemm_issue_B(ns, tid, Bth, Btl, nBase, (kc + 1) * 32);
            gemm_issue_A(ns, tid, Ah, Al, mBase, (kc + 1) * 32);
            CP_COMMIT();
        }
        if (kc < 7) { CP_WAIT1(); } else { CP_WAIT0(); }
        __syncthreads();

        uint32_t st = sb + (kc & 1) * STAGE_B;
#pragma unroll
        for (int ks = 0; ks < 2; ks++) {
            int lrow = lane & 15;
            int lcol = ks * 16 + (lane >> 4) * 8;
            uint32_t ah[2][4], al[2][4];
#pragma unroll
            for (int mt = 0; mt < 2; mt++) {
                int row = warpM * 32 + mt * 16 + lrow;
                uint32_t ad = st + (uint32_t)((row * GPAD + lcol) * 2);
                ldmatrix_x4(ah[mt], ad);
                ldmatrix_x4(al[mt], ad + TILE_B);
            }
#pragma unroll
            for (int nt2 = 0; nt2 < 4; nt2++) {
                int row = warpN * 64 + nt2 * 16 + lrow;
                uint32_t bd = st + 2 * TILE_B + (uint32_t)((row * GPAD + lcol) * 2);
                uint32_t bh[4], bl[4];
                ldmatrix_x4(bh, bd);
                ldmatrix_x4(bl, bd + TILE_B);
#pragma unroll
                for (int mt = 0; mt < 2; mt++) {
                    mma16816(acc[mt][nt2 * 2 + 0], ah[mt], bh[0], bh[2]);
                    mma16816(acc[mt][nt2 * 2 + 0], ah[mt], bl[0], bl[2]);
                    mma16816(acc[mt][nt2 * 2 + 0], al[mt], bh[0], bh[2]);
                    mma16816(acc[mt][nt2 * 2 + 1], ah[mt], bh[1], bh[3]);
                    mma16816(acc[mt][nt2 * 2 + 1], ah[mt], bl[1], bl[3]);
                    mma16816(acc[mt][nt2 * 2 + 1], al[mt], bh[1], bh[3]);
                }
            }
        }
        __syncthreads();
    }

    PDL_TRIGGER();   // successor may start launching; epilogue still to run

    int g = lane >> 2, tig = lane & 3;
#pragma unroll
    for (int mt = 0; mt < 2; mt++) {
#pragma unroll
        for (int nt = 0; nt < 8; nt++) {
            int row0 = mBase + warpM * 32 + mt * 16 + g;
            int col  = nBase + warpN * 64 + nt * 8 + tig * 2;
            float v0 = acc[mt][nt][0], v1 = acc[mt][nt][1];
            float v2 = acc[mt][nt][2], v3 = acc[mt][nt][3];
            if (MODE == 2) {
                float bb0 = bias[col], bb1 = bias[col + 1];
                v0 = gelu_tanh(v0 + bb0); v1 = gelu_tanh(v1 + bb1);
                v2 = gelu_tanh(v2 + bb0); v3 = gelu_tanh(v3 + bb1);
            }
            if (MODE == 3) {
                v0 *= ATTN_SCALE; v1 *= ATTN_SCALE;
                v2 *= ATTN_SCALE; v3 *= ATTN_SCALE;
            }
            uint32_t hp01, lp01, hp23, lp23;
            split2(v0, v1, hp01, lp01);
            split2(v2, v3, hp23, lp23);
            *reinterpret_cast<uint32_t*>(Ch + (size_t)row0 * ldC + col) = hp01;
            *reinterpret_cast<uint32_t*>(Ch + (size_t)(row0 + 8) * ldC + col) = hp23;
            *reinterpret_cast<uint32_t*>(Cl + (size_t)row0 * ldC + col) = lp01;
            *reinterpret_cast<uint32_t*>(Cl + (size_t)(row0 + 8) * ldC + col) = lp23;
        }
    }
}

// ---------------------------------------------------------------------------
// Merged Q + K|V projection launch.
// ---------------------------------------------------------------------------
__global__ __launch_bounds__(256, 2)
void qkv_proj_kernel(const __nv_bfloat16* __restrict__ qnh, const __nv_bfloat16* __restrict__ qnl,
                     const __nv_bfloat16* __restrict__ knh, const __nv_bfloat16* __restrict__ knl,
                     const __nv_bfloat16* __restrict__ Wqh, const __nv_bfloat16* __restrict__ Wql,
                     const __nv_bfloat16* __restrict__ Wkvh, const __nv_bfloat16* __restrict__ Wkvl,
                     __nv_bfloat16* __restrict__ Qh, __nv_bfloat16* __restrict__ Ql,
                     __nv_bfloat16* __restrict__ KVh, __nv_bfloat16* __restrict__ KVl) {
    extern __shared__ char smem[];
    int bx = blockIdx.x;
    if (bx < (B * NK / 128) * 4) {
        gemm_body<0>(smem, knh, knl, Wkvh, Wkvl, nullptr,
                     KVh, KVl, 512, (bx >> 2) * 128, (bx & 3) * 128);
    } else {
        int b2 = bx - (B * NK / 128) * 4;
        gemm_body<3>(smem, qnh, qnl, Wqh, Wql, nullptr,
                     Qh, Ql, 256, (b2 >> 1) * 128, (b2 & 1) * 128);
    }
}

// W1 GEMM (bias + gelu)
__global__ __launch_bounds__(256, 2)
void gemm_w1_kernel(const __nv_bfloat16* __restrict__ Ah, const __nv_bfloat16* __restrict__ Al,
                    const __nv_bfloat16* __restrict__ Bth, const __nv_bfloat16* __restrict__ Btl,
                    const float* __restrict__ bias,
                    __nv_bfloat16* __restrict__ Ch, __nv_bfloat16* __restrict__ Cl) {
    extern __shared__ char smem[];
    gemm_body<2>(smem, Ah, Al, Bth, Btl, bias, Ch, Cl, 256,
                 blockIdx.x * 128, blockIdx.y * 128);
}

// ---------------------------------------------------------------------------
// GEMM 64(M) x 256(N) tile with fused row-LayerNorm epilogue. PDL-aware.
// ---------------------------------------------------------------------------
#define G2A (64 * GPAD * 2)
#define G2B (256 * GPAD * 2)
#define G2_STAGE (2 * G2A + 2 * G2B)
#define G2_SMEM (2 * G2_STAGE)

__device__ __forceinline__ void g2_issue_B(
    uint32_t stage, int tid,
    const __nv_bfloat16* Bh, const __nv_bfloat16* Bl, int k0)
{
#pragma unroll
    for (int it = 0; it < 4; it++) {
        int seg = tid + it * 256;
        int row = seg >> 2, j = seg & 3;
        uint32_t off = (uint32_t)((row * GPAD + j * 8) * 2);
        size_t go = (size_t)row * 256 + k0 + j * 8;
        CP_ASYNC16(stage + 2 * G2A + off, Bh + go);
        CP_ASYNC16(stage + 2 * G2A + G2B + off, Bl + go);
    }
}

__device__ __forceinline__ void g2_issue_A(
    uint32_t stage, int tid,
    const __nv_bfloat16* Ah, const __nv_bfloat16* Al,
    int mBase, int k0)
{
    int row = tid >> 2, j = tid & 3;
    uint32_t off = (uint32_t)((row * GPAD + j * 8) * 2);
    size_t go = (size_t)(mBase + row) * 256 + k0 + j * 8;
    CP_ASYNC16(stage + off, Ah + go);
    CP_ASYNC16(stage + G2A + off, Al + go);
}

__device__ __forceinline__ void cta_ln_stats(
    float (&acc)[2][8][4], char* smemraw,
    int warpM, int warpN, int g, int tig,
    float (&mean)[2][2], float (&rstd)[2][2])
{
    float* redS = reinterpret_cast<float*>(smemraw);
    float* redQ = redS + 256;
    __syncthreads();
    float ps[2][2], pq[2][2];
#pragma unroll
    for (int mt = 0; mt < 2; mt++)
#pragma unroll
        for (int hf = 0; hf < 2; hf++) {
            float s = 0.f, q = 0.f;
#pragma unroll
            for (int nt = 0; nt < 8; nt++) {
                float a = acc[mt][nt][hf * 2], b = acc[mt][nt][hf * 2 + 1];
                s += a + b; q += a * a + b * b;
            }
            ps[mt][hf] = s; pq[mt][hf] = q;
        }
#pragma unroll
    for (int o = 1; o <= 2; o <<= 1) {
#pragma unroll
        for (int mt = 0; mt < 2; mt++)
#pragma unroll
            for (int hf = 0; hf < 2; hf++) {
                ps[mt][hf] += __shfl_xor_sync(0xffffffffu, ps[mt][hf], o);
                pq[mt][hf] += __shfl_xor_sync(0xffffffffu, pq[mt][hf], o);
            }
    }
    if (tig == 0) {
#pragma unroll
        for (int mt = 0; mt < 2; mt++)
#pragma unroll
            for (int hf = 0; hf < 2; hf++) {
                int lr = warpM * 32 + mt * 16 + g + hf * 8;
                redS[lr * 4 + warpN] = ps[mt][hf];
                redQ[lr * 4 + warpN] = pq[mt][hf];
            }
    }
    __syncthreads();
#pragma unroll
    for (int mt = 0; mt < 2; mt++)
#pragma unroll
        for (int hf = 0; hf < 2; hf++) {
            int lr = warpM * 32 + mt * 16 + g + hf * 8;
            float S = redS[lr * 4] + redS[lr * 4 + 1] + redS[lr * 4 + 2] + redS[lr * 4 + 3];
            float Q = redQ[lr * 4] + redQ[lr * 4 + 1] + redQ[lr * 4 + 2] + redQ[lr * 4 + 3];
            float m = S * (1.0f / D);
            float v = Q * (1.0f / D) - m * m;
            mean[mt][hf] = m;
            rstd[mt][hf] = rsqrtf(v + 1e-5f);
        }
}

template <int RES>
__global__ __launch_bounds__(256, 2)
void gemm_ln_kernel(const __nv_bfloat16* __restrict__ Ah, const __nv_bfloat16* __restrict__ Al,
                    const __nv_bfloat16* __restrict__ Bth, const __nv_bfloat16* __restrict__ Btl,
                    const float* __restrict__ bias,
                    const float* __restrict__ ln1s, const float* __restrict__ ln1b,
                    const float* __restrict__ ln2s, const float* __restrict__ ln2b,
                    const __nv_bfloat16* __restrict__ hh, const __nv_bfloat16* __restrict__ hl,
                    const int* __restrict__ qidx,
                    __nv_bfloat16* __restrict__ Oh, __nv_bfloat16* __restrict__ Ol,
                    float* __restrict__ outp) {
    extern __shared__ char smem[];
    const uint32_t sb = smem_u32(smem);

    int tid  = threadIdx.x;
    int wid  = tid >> 5, lane = tid & 31;
    int warpM = wid & 1;
    int warpN = wid >> 1;
    int mBase = blockIdx.x * 64;
    int g = lane >> 2, tig = lane & 3;

    float acc[2][8][4];
#pragma unroll
    for (int i = 0; i < 2; i++)
#pragma unroll
        for (int j = 0; j < 8; j++)
#pragma unroll
            for (int k = 0; k < 4; k++) acc[i][j][k] = 0.f;

    // PDL: weights pre-sync, A post-sync
    g2_issue_B(sb, tid, Bth, Btl, 0);
    PDL_SYNC();
    g2_issue_A(sb, tid, Ah, Al, mBase, 0);
    CP_COMMIT();

    for (int kc = 0; kc < 8; kc++) {
        if (kc < 7) {
            uint32_t ns = sb + ((kc + 1) & 1) * G2_STAGE;
            g2_issue_B(ns, tid, Bth, Btl, (kc + 1) * 32);
            g2_issue_A(ns, tid, Ah, Al, mBase, (kc + 1) * 32);
            CP_COMMIT();
        }
        if (kc < 7) { CP_WAIT1(); } else { CP_WAIT0(); }
        __syncthreads();

        uint32_t st = sb + (kc & 1) * G2_STAGE;
#pragma unroll
        for (int ks = 0; ks < 2; ks++) {
            int lrow = lane & 15;
            int lcol = ks * 16 + (lane >> 4) * 8;
            uint32_t ah[2][4], al[2][4];
#pragma unroll
            for (int mt = 0; mt < 2; mt++) {
                int row = warpM * 32 + mt * 16 + lrow;
                uint32_t ad = st + (uint32_t)((row * GPAD + lcol) * 2);
                ldmatrix_x4(ah[mt], ad);
                ldmatrix_x4(al[mt], ad + G2A);
            }
#pragma unroll
            for (int nt2 = 0; nt2 < 4; nt2++) {
                int row = warpN * 64 + nt2 * 16 + lrow;
                uint32_t bd = st + 2 * G2A + (uint32_t)((row * GPAD + lcol) * 2);
                uint32_t bh[4], bl[4];
                ldmatrix_x4(bh, bd);
                ldmatrix_x4(bl, bd + G2B);
#pragma unroll
                for (int mt = 0; mt < 2; mt++) {
                    mma16816(acc[mt][nt2 * 2 + 0], ah[mt], bh[0], bh[2]);
                    mma16816(acc[mt][nt2 * 2 + 0], ah[mt], bl[0], bl[2]);
                    mma16816(acc[mt][nt2 * 2 + 0], al[mt], bh[0], bh[2]);
                    mma16816(acc[mt][nt2 * 2 + 1], ah[mt], bh[1], bh[3]);
                    mma16816(acc[mt][nt2 * 2 + 1], ah[mt], bl[1], bl[3]);
                    mma16816(acc[mt][nt2 * 2 + 1], al[mt], bh[1], bh[3]);
                }
            }
        }
        __syncthreads();
    }

    PDL_TRIGGER();

    float mean[2][2], rstd[2][2];

    if (RES == 1) {
#pragma unroll
        for (int mt = 0; mt < 2; mt++)
#pragma unroll
            for (int nt = 0; nt < 8; nt++) {
                int col = warpN * 64 + nt * 8 + tig * 2;
                float bb0 = __ldg(bias + col), bb1 = __ldg(bias + col + 1);
#pragma unroll
                for (int hf = 0; hf < 2; hf++) {
                    int gr = mBase + warpM * 32 + mt * 16 + g + hf * 8;
                    size_t o = (size_t)gr * D + col;
                    float2 hv = bf2_sum(*reinterpret_cast<const uint32_t*>(hh + o),
                                        *reinterpret_cast<const uint32_t*>(hl + o));
                    acc[mt][nt][hf * 2 + 0] += bb0 + hv.x;
                    acc[mt][nt][hf * 2 + 1] += bb1 + hv.y;
                }
            }
    }

    cta_ln_stats(acc, smem, warpM, warpN, g, tig, mean, rstd);
#pragma unroll
    for (int mt = 0; mt < 2; mt++)
#pragma unroll
        for (int nt = 0; nt < 8; nt++) {
            int col = warpN * 64 + nt * 8 + tig * 2;
            float s0 = __ldg(ln1s + col), s1 = __ldg(ln1s + col + 1);
            float c0 = __ldg(ln1b + col), c1 = __ldg(ln1b + col + 1);
#pragma unroll
            for (int hf = 0; hf < 2; hf++) {
                acc[mt][nt][hf * 2 + 0] =
                    (acc[mt][nt][hf * 2 + 0] - mean[mt][hf]) * rstd[mt][hf] * s0 + c0;
                acc[mt][nt][hf * 2 + 1] =
                    (acc[mt][nt][hf * 2 + 1] - mean[mt][hf]) * rstd[mt][hf] * s1 + c1;
            }
        }

    if (RES == 0) {
#pragma unroll
        for (int mt = 0; mt < 2; mt++)
#pragma unroll
            for (int nt = 0; nt < 8; nt++) {
                int col = warpN * 64 + nt * 8 + tig * 2;
#pragma unroll
                for (int hf = 0; hf < 2; hf++) {
                    int gr = mBase + warpM * 32 + mt * 16 + g + hf * 8;
                    uint32_t hp, lp;
                    split2(acc[mt][nt][hf * 2], acc[mt][nt][hf * 2 + 1], hp, lp);
                    *reinterpret_cast<uint32_t*>(Oh + (size_t)gr * D + col) = hp;
                    *reinterpret_cast<uint32_t*>(Ol + (size_t)gr * D + col) = lp;
                }
            }
    } else {
        cta_ln_stats(acc, smem, warpM, warpN, g, tig, mean, rstd);
        int sidx[2][2], bidx[2][2];
#pragma unroll
        for (int mt = 0; mt < 2; mt++)
#pragma unroll
            for (int hf = 0; hf < 2; hf++) {
                int gr = mBase + warpM * 32 + mt * 16 + g + hf * 8;
                bidx[mt][hf] = gr / NQ;
                sidx[mt][hf] = __ldg(qidx + (gr % NQ));
            }
#pragma unroll
        for (int mt = 0; mt < 2; mt++)
#pragma unroll
            for (int nt = 0; nt < 8; nt++) {
                int col = warpN * 64 + nt * 8 + tig * 2;
                float s0 = __ldg(ln2s + col), s1 = __ldg(ln2s + col + 1);
                float c0 = __ldg(ln2b + col), c1 = __ldg(ln2b + col + 1);
#pragma unroll
                for (int hf = 0; hf < 2; hf++) {
                    float z0 = (acc[mt][nt][hf * 2 + 0] - mean[mt][hf]) * rstd[mt][hf] * s0 + c0;
                    float z1 = (acc[mt][nt][hf * 2 + 1] - mean[mt][hf]) * rstd[mt][hf] * s1 + c1;
                    size_t o = ((size_t)bidx[mt][hf] * NS + sidx[mt][hf]) * D + col;
                    atomicAdd(&outp[o], z0);
                    atomicAdd(&outp[o + 1], z1);
                }
            }
    }
}

// ---------------------------------------------------------------------------
// Fused flash attention (static softmax, Q pre-scaled), Round-9 numerics.
// 128-query tile, 256 threads, 2 CTAs/SM (measured-best configuration).
// PDL: mask chunk-0 staged pre-sync (static); Q/KV post-sync.
// ---------------------------------------------------------------------------
#define APAD 72
#define A_KH 0
#define A_KL 9216
#define A_VH 18432
#define A_VL 27648
#define A_MS 36864
#define A_STAGE 47104
#define ATTN_SMEM_BYTES (2 * A_STAGE)

__device__ __forceinline__ void attn_stage_mask(
    uint32_t st, int tid, const unsigned char* maskb, int q0, int kb)
{
#pragma unroll
    for (int it = 0; it < 2; it++) {
        int seg = tid + it * 256;
        int r = seg >> 2, j = seg & 3;
        CP_ASYNC16(st + A_MS + (uint32_t)(r * 80 + j * 16),
                   maskb + (size_t)(q0 + r) * NK + kb + j * 16);
    }
}

__device__ __forceinline__ void attn_stage_kv(
    uint32_t st, int tid,
    const __nv_bfloat16* KVh, const __nv_bfloat16* KVl,
    int b, int h, int kb)
{
#pragma unroll
    for (int it = 0; it < 2; it++) {
        int seg = tid + it * 256;
        int r = seg >> 3, j = seg & 7;
        size_t rowb = ((size_t)(b * NK + kb + r)) * 512 + h * DH + j * 8;
        uint32_t off = (uint32_t)((r * APAD + j * 8) * 2);
        CP_ASYNC16(st + A_KH + off, KVh + rowb);
        CP_ASYNC16(st + A_KL + off, KVl + rowb);
        CP_ASYNC16(st + A_VH + off, KVh + rowb + 256);
        CP_ASYNC16(st + A_VL + off, KVl + rowb + 256);
    }
}

__global__ __launch_bounds__(256, 2)
void attn_mma_kernel(const __nv_bfloat16* __restrict__ Qh, const __nv_bfloat16* __restrict__ Ql,
                     const __nv_bfloat16* __restrict__ KVh, const __nv_bfloat16* __restrict__ KVl,
                     const unsigned char* __restrict__ maskb,
                     __nv_bfloat16* __restrict__ ctxh, __nv_bfloat16* __restrict__ ctxl) {
    extern __shared__ char smem[];
    const uint32_t sb = smem_u32(smem);

    int tid = threadIdx.x, wid = tid >> 5, lane = tid & 31;
    int q0 = blockIdx.x * 128, h = blockIdx.y, b = blockIdx.z;
    int g = lane >> 2, tig = lane & 3;
    int lrow = lane & 15, lco = (lane >> 4) * 8;

    // PDL: mask is static -> stage chunk 0 mask before dependency sync
    attn_stage_mask(sb, tid, maskb, q0, 0);
    PDL_SYNC();
    attn_stage_kv(sb, tid, KVh, KVl, b, h, 0);
    CP_COMMIT();

    uint32_t qah[4][4], qal[4][4];
#pragma unroll
    for (int ks = 0; ks < 4; ks++) {
#pragma unroll
        for (int i = 0; i < 4; i++) {
            int row = q0 + wid * 16 + g + (i & 1) * 8;
            int col = h * DH + ks * 16 + tig * 2 + (i >> 1) * 8;
            size_t o = ((size_t)(b * NQ + row)) * D + col;
            qah[ks][i] = *reinterpret_cast<const uint32_t*>(Qh + o);
            qal[ks][i] = *reinterpret_cast<const uint32_t*>(Ql + o);
        }
    }

    float l0 = 0.f, l1 = 0.f;
    float oacc[8][4];
#pragma unroll
    for (int j = 0; j < 8; j++)
#pragma unroll
        for (int k = 0; k < 4; k++) oacc[j][k] = 0.f;

    for (int c = 0; c < 16; c++) {
        if (c < 15) {
            uint32_t ns = sb + ((c + 1) & 1) * A_STAGE;
            attn_stage_mask(ns, tid, maskb, q0, (c + 1) * 64);
            attn_stage_kv(ns, tid, KVh, KVl, b, h, (c + 1) * 64);
            CP_COMMIT();
        }
        if (c < 15) { CP_WAIT1(); } else { CP_WAIT0(); }
        __syncthreads();

        uint32_t st = sb + (c & 1) * A_STAGE;
        const unsigned char* msp = reinterpret_cast<const unsigned char*>(
            smem + (c & 1) * A_STAGE + A_MS);

        // S = Q K^T (split-3)
        float sacc[8][4];
#pragma unroll
        for (int j = 0; j < 8; j++)
#pragma unroll
            for (int k = 0; k < 4; k++) sacc[j][k] = 0.f;
#pragma unroll
        for (int ks = 0; ks < 4; ks++) {
#pragma unroll
            for (int nt = 0; nt < 4; nt++) {
                uint32_t bh[4], bl[4];
                uint32_t off = (uint32_t)(((nt * 16 + lrow) * APAD + ks * 16 + lco) * 2);
                ldmatrix_x4(bh, st + A_KH + off);
                ldmatrix_x4(bl, st + A_KL + off);
                mma16816(sacc[nt * 2 + 0], qah[ks], bh[0], bh[2]);
                mma16816(sacc[nt * 2 + 0], qah[ks], bl[0], bl[2]);
                mma16816(sacc[nt * 2 + 0], qal[ks], bh[0], bh[2]);
                mma16816(sacc[nt * 2 + 1], qah[ks], bh[1], bh[3]);
                mma16816(sacc[nt * 2 + 1], qah[ks], bl[1], bl[3]);
                mma16816(sacc[nt * 2 + 1], qal[ks], bh[1], bh[3]);
            }
        }

        // p = exp(s) masked->0; P split hi/lo; l in fp32 (unrounded)
        int qr0 = wid * 16 + g, qr1 = qr0 + 8;
        uint32_t pa[4][4], pl[4][4];
#pragma unroll
        for (int j = 0; j < 8; j++) {
            int col = j * 8 + 2 * tig;
            float p0 = msp[qr0 * 80 + col]     ? __expf(sacc[j][0]) : 0.f;
            float p1 = msp[qr0 * 80 + col + 1] ? __expf(sacc[j][1]) : 0.f;
            float p2 = msp[qr1 * 80 + col]     ? __expf(sacc[j][2]) : 0.f;
            float p3 = msp[qr1 * 80 + col + 1] ? __expf(sacc[j][3]) : 0.f;
            l0 += p0 + p1; l1 += p2 + p3;
            int kc = j >> 1, o2 = (j & 1) * 2;
            uint32_t hp, lp;
            split2(p0, p1, hp, lp);
            pa[kc][o2 + 0] = hp; pl[kc][o2 + 0] = lp;
            split2(p2, p3, hp, lp);
            pa[kc][o2 + 1] = hp; pl[kc][o2 + 1] = lp;
        }

        // O += P V  (split-3)
        int vro = ((lane >> 4) << 3) + (lane & 7);
        int vcb = ((lane >> 3) & 1) << 3;
#pragma unroll
        for (int kc = 0; kc < 4; kc++) {
            int vr = 16 * kc + vro;
#pragma unroll
            for (int vt = 0; vt < 4; vt++) {
                uint32_t vh[4], vl[4];
                uint32_t off = (uint32_t)((vr * APAD + vt * 16 + vcb) * 2);
                ldmatrix_x4_t(vh, st + A_VH + off);
                ldmatrix_x4_t(vl, st + A_VL + off);
                mma16816(oacc[vt * 2 + 0], pa[kc], vh[0], vh[2]);
                mma16816(oacc[vt * 2 + 0], pa[kc], vl[0], vl[2]);
                mma16816(oacc[vt * 2 + 0], pl[kc], vh[0], vh[2]);
                mma16816(oacc[vt * 2 + 1], pa[kc], vh[1], vh[3]);
                mma16816(oacc[vt * 2 + 1], pa[kc], vl[1], vl[3]);
                mma16816(oacc[vt * 2 + 1], pl[kc], vh[1], vh[3]);
            }
        }
        __syncthreads();
    }

    PDL_TRIGGER();

    l0 += __shfl_xor_sync(0xffffffffu, l0, 1);
    l0 += __shfl_xor_sync(0xffffffffu, l0, 2);
    l1 += __shfl_xor_sync(0xffffffffu, l1, 1);
    l1 += __shfl_xor_sync(0xffffffffu, l1, 2);

    float inv0 = 1.0f / l0, inv1 = 1.0f / l1;
#pragma unroll
    for (int j = 0; j < 8; j++) {
        int col = h * DH + j * 8 + 2 * tig;
        size_t r0 = ((size_t)(b * NQ + q0 + wid * 16 + g)) * D + col;
        uint32_t hp, lp;
        split2(oacc[j][0] * inv0, oacc[j][1] * inv0, hp, lp);
        *reinterpret_cast<uint32_t*>(ctxh + r0) = hp;
        *reinterpret_cast<uint32_t*>(ctxl + r0) = lp;
        split2(oacc[j][2] * inv1, oacc[j][3] * inv1, hp, lp);
        *reinterpret_cast<uint32_t*>(ctxh + r0 + 8 * D) = hp;
        *reinterpret_cast<uint32_t*>(ctxl + r0 + 8 * D) = lp;
    }
}

// ---------------------------------------------------------------------------
// launch
// ---------------------------------------------------------------------------
extern "C" void kernel_launch(void* const* d_in, const int* in_sizes, int n_in,
                              void* d_out, int out_size) {
    const float* update_tensor = (const float*)d_in[0];
    const float* emb   = (const float*)d_in[1];
    const float* mask  = (const float*)d_in[2];
    const float* Wq    = (const float*)d_in[3];
    const float* Wk    = (const float*)d_in[4];
    const float* Wv    = (const float*)d_in[5];
    const float* Wo    = (const float*)d_in[6];
    const float* W1    = (const float*)d_in[7];
    const float* b1    = (const float*)d_in[8];
    const float* W2    = (const float*)d_in[9];
    const float* b2    = (const float*)d_in[10];
    const float* sys_s = (const float*)d_in[11];
    const float* sys_b = (const float*)d_in[12];
    const float* eff_s = (const float*)d_in[13];
    const float* eff_b = (const float*)d_in[14];
    const float* in_s  = (const float*)d_in[15];
    const float* in_b  = (const float*)d_in[16];
    const float* out_s = (const float*)d_in[17];
    const float* out_b = (const float*)d_in[18];
    const int*   qidx  = (const int*)d_in[19];
    const int*   kidx  = (const int*)d_in[20];
    float* outp = (float*)d_out;

    __nv_bfloat16 *p_wh, *p_wl, *p_qnh, *p_qnl, *p_knh, *p_knl;
    __nv_bfloat16 *p_Qh, *p_Ql, *p_KVh, *p_KVl;
    __nv_bfloat16 *p_ctxh, *p_ctxl, *p_hh, *p_hl, *p_gh, *p_gl;
    unsigned char* p_mb;
    cudaGetSymbolAddress((void**)&p_wh,   g_Wt_hi);
    cudaGetSymbolAddress((void**)&p_wl,   g_Wt_lo);
    cudaGetSymbolAddress((void**)&p_qnh,  g_qnh);
    cudaGetSymbolAddress((void**)&p_qnl,  g_qnl);
    cudaGetSymbolAddress((void**)&p_knh,  g_knh);
    cudaGetSymbolAddress((void**)&p_knl,  g_knl);
    cudaGetSymbolAddress((void**)&p_Qh,   g_Qh);
    cudaGetSymbolAddress((void**)&p_Ql,   g_Ql);
    cudaGetSymbolAddress((void**)&p_KVh,  g_KVh);
    cudaGetSymbolAddress((void**)&p_KVl,  g_KVl);
    cudaGetSymbolAddress((void**)&p_ctxh, g_ctxh);
    cudaGetSymbolAddress((void**)&p_ctxl, g_ctxl);
    cudaGetSymbolAddress((void**)&p_hh,   g_hh);
    cudaGetSymbolAddress((void**)&p_hl,   g_hl);
    cudaGetSymbolAddress((void**)&p_gh,   g_gh);
    cudaGetSymbolAddress((void**)&p_gl,   g_gl);
    cudaGetSymbolAddress((void**)&p_mb,   g_maskb);

    cudaFuncSetAttribute(qkv_proj_kernel, cudaFuncAttributeMaxDynamicSharedMemorySize, GEMM_SMEM_BYTES);
    cudaFuncSetAttribute(gemm_w1_kernel,  cudaFuncAttributeMaxDynamicSharedMemorySize, GEMM_SMEM_BYTES);
    cudaFuncSetAttribute(gemm_ln_kernel<0>, cudaFuncAttributeMaxDynamicSharedMemorySize, G2_SMEM);
    cudaFuncSetAttribute(gemm_ln_kernel<1>, cudaFuncAttributeMaxDynamicSharedMemorySize, G2_SMEM);
    cudaFuncSetAttribute(attn_mma_kernel, cudaFuncAttributeMaxDynamicSharedMemorySize, ATTN_SMEM_BYTES);

    init_kernel<<<(B * NS * D / 4) / 256, 256>>>(outp);
    maskb_kernel<<<(LVL * NQ * NK / 4) / 256, 256>>>(mask, p_mb);
    {
        WPtrs ws;
        ws.w[0] = Wq; ws.w[1] = Wk; ws.w[2] = Wv;
        ws.w[3] = Wo; ws.w[4] = W1; ws.w[5] = W2;
        prep_w_all_kernel<<<dim3(8, 8, 6), dim3(32, 8)>>>(ws, p_wh, p_wl);
    }

    const int QKV_GRID = (B * NK / 128) * 4 + (B * NQ / 128) * 2;   // 1280

    cudaLaunchAttribute pdlAttr[1];
    pdlAttr[0].id = cudaLaunchAttributeProgrammaticStreamSerialization;
    pdlAttr[0].val.programmaticStreamSerializationAllowed = 1;

    cudaLaunchConfig_t cGather = {};
    cGather.gridDim = dim3(B * (NQ + NK) / 8, 1, 1);
    cGather.blockDim = dim3(256, 1, 1);
    cGather.attrs = pdlAttr; cGather.numAttrs = 1;

    cudaLaunchConfig_t cQkv = {};
    cQkv.gridDim = dim3(QKV_GRID, 1, 1);
    cQkv.blockDim = dim3(256, 1, 1);
    cQkv.dynamicSmemBytes = GEMM_SMEM_BYTES;
    cQkv.attrs = pdlAttr; cQkv.numAttrs = 1;

    cudaLaunchConfig_t cAttn = {};
    cAttn.gridDim = dim3(NQ / 128, H, B);
    cAttn.blockDim = dim3(256, 1, 1);
    cAttn.dynamicSmemBytes = ATTN_SMEM_BYTES;
    cAttn.attrs = pdlAttr; cAttn.numAttrs = 1;

    cudaLaunchConfig_t cLn = {};
    cLn.gridDim = dim3(B * NQ / 64, 1, 1);
    cLn.blockDim = dim3(256, 1, 1);
    cLn.dynamicSmemBytes = G2_SMEM;
    cLn.attrs = pdlAttr; cLn.numAttrs = 1;

    cudaLaunchConfig_t cW1 = {};
    cW1.gridDim = dim3(B * NQ / 128, 2, 1);
    cW1.blockDim = dim3(256, 1, 1);
    cW1.dynamicSmemBytes = GEMM_SMEM_BYTES;
    cW1.attrs = pdlAttr; cW1.numAttrs = 1;

    for (int l = 0; l < LVL; l++) {
        const int* qi = qidx + l * NQ;
        const int* ki = kidx + l * NK;
        const unsigned char* mb = p_mb + (size_t)l * NQ * NK;

        cudaLaunchKernelEx(&cGather, gather_ln_kernel,
                           emb, update_tensor, (const float*)outp,
                           sys_s, sys_b, qi, ki,
                           p_qnh, p_qnl, p_knh, p_knl);

        cudaLaunchKernelEx(&cQkv, qkv_proj_kernel,
                           (const __nv_bfloat16*)p_qnh, (const __nv_bfloat16*)p_qnl,
                           (const __nv_bfloat16*)p_knh, (const __nv_bfloat16*)p_knl,
                           (const __nv_bfloat16*)(p_wh + 0 * 65536), (const __nv_bfloat16*)(p_wl + 0 * 65536),
                           (const __nv_bfloat16*)(p_wh + 1 * 65536), (const __nv_bfloat16*)(p_wl + 1 * 65536),
                           p_Qh, p_Ql, p_KVh, p_KVl);

        cudaLaunchKernelEx(&cAttn, attn_mma_kernel,
                           (const __nv_bfloat16*)p_Qh, (const __nv_bfloat16*)p_Ql,
                           (const __nv_bfloat16*)p_KVh, (const __nv_bfloat16*)p_KVl,
                           (const unsigned char*)mb, p_ctxh, p_ctxl);

        cudaLaunchKernelEx(&cLn, gemm_ln_kernel<0>,
                           (const __nv_bfloat16*)p_ctxh, (const __nv_bfloat16*)p_ctxl,
                           (const __nv_bfloat16*)(p_wh + 3 * 65536), (const __nv_bfloat16*)(p_wl + 3 * 65536),
                           (const float*)nullptr, in_s, in_b,
                           (const float*)nullptr, (const float*)nullptr,
                           (const __nv_bfloat16*)nullptr, (const __nv_bfloat16*)nullptr,
                           (const int*)nullptr, p_hh, p_hl, (float*)nullptr);

        cudaLaunchKernelEx(&cW1, gemm_w1_kernel,
                           (const __nv_bfloat16*)p_hh, (const __nv_bfloat16*)p_hl,
                           (const __nv_bfloat16*)(p_wh + 4 * 65536), (const __nv_bfloat16*)(p_wl + 4 * 65536),
                           b1, p_gh, p_gl);

        cudaLaunchKernelEx(&cLn, gemm_ln_kernel<1>,
                           (const __nv_bfloat16*)p_gh, (const __nv_bfloat16*)p_gl,
                           (const __nv_bfloat16*)(p_wh + 5 * 65536), (const __nv_bfloat16*)(p_wl + 5 * 65536),
                           b2, out_s, out_b, eff_s, eff_b,
                           (const __nv_bfloat16*)p_hh, (const __nv_bfloat16*)p_hl,
                           qi, (__nv_bfloat16*)nullptr, (__nv_bfloat16*)nullptr, outp);
    }
}